// round 10
// baseline (speedup 1.0000x reference)
#include <cuda_runtime.h>
#include <math.h>

// Problem constants (fixed by the reference)
#define TT   256
#define BB   128
#define CC   512
#define HH   512
#define LL   2
#define KDIM 1024          // C+H == 2H
#define NG   2048          // 4H
#define BHN  (BB*HH)       // 65536
#define NCTA 128           // persistent grid (<= 148 SMs -> all co-resident)

// smem double buffer: per buffer As[32][68] (2176) + Bs[32][33] (1056) = 3232 floats
#define ASZ  2176
#define BUFSZ 3232

// ---------------- scratch (static __device__, no allocations) ----------------
__device__ float d_y0[(size_t)TT*BB*HH];  // layer-0 output (64 MB)
__device__ float d_Z [(size_t)TT*BB*NG];  // precomputed x-part of outer gates (+bias)
__device__ float d_h[BHN];                // outer hidden
__device__ float d_c[BHN];                // outer cell state
__device__ float d_hi[2][BHN];            // inner hidden (ping-pong)
__device__ float d_ci[BHN];               // inner cell state
__device__ float d_cell[BHN];             // outer candidate cell (input to inner GEMM)
__device__ float d_sigo[BHN];             // sigmoid(outer o-gate)
__device__ unsigned int g_bar;            // grid barrier counter (reset per launch)

__device__ __forceinline__ float sigmf(float x) { return 1.0f / (1.0f + expf(-x)); }

__global__ void reset_bar_kernel() { g_bar = 0u; }

// Software grid barrier: all NCTA CTAs co-resident; monotonic counter.
__device__ __forceinline__ void gsync(unsigned int& epoch)
{
    ++epoch;
    __syncthreads();
    if (threadIdx.x == 0) {
        __threadfence();
        atomicAdd(&g_bar, 1u);
        const unsigned int target = epoch * (unsigned int)NCTA;
        while (*(volatile unsigned int*)&g_bar < target) { }
        __threadfence();
    }
    __syncthreads();
}

__device__ __forceinline__ float2 unpack64(unsigned long long v)
{
    float2 r;
    asm("mov.b64 {%0, %1}, %2;" : "=f"(r.x), "=f"(r.y) : "l"(v));
    return r;
}

// ---------------- GEMM tile ----------------
// out[b, n] = sum_k A[b,k] * W[n,k]; A row stride 512; W row stride KDIM.
// CTA tile: 64 rows (m0) x 32 cols (4 gates x 8 j at j0). 256 threads:
//   warp tm = tid>>5 owns rows m0 + tm*8 .. +7  (A reads = warp-broadcast)
//   lane ln = tid&31 owns column ln             (B read  = conflict-free LDS.32)
// acc[p] = f32x2 pair for rows (tm*8+2p, tm*8+2p+1). KT = # of 32-wide K tiles.
template<int KT>
__device__ __forceinline__ void gemm_tile(const float* __restrict__ A0,
                                          const float* __restrict__ A1,
                                          const float* __restrict__ W,
                                          float* smem,
                                          int m0, int wrow, int lrow, int lk4,
                                          int tm, int ln,
                                          unsigned long long acc[4])
{
    const float4* Wp = reinterpret_cast<const float4*>(W + (size_t)wrow * KDIM) + lk4;

    float4 a0 = *reinterpret_cast<const float4*>(A0 + (size_t)(m0      + lrow) * 512 + lk4 * 4);
    float4 a1 = *reinterpret_cast<const float4*>(A0 + (size_t)(m0 + 32 + lrow) * 512 + lk4 * 4);
    float4 wv = Wp[0];

    #pragma unroll 1
    for (int kt = 0; kt < KT; ++kt) {
        float* As = smem + (kt & 1) * BUFSZ;
        float* Bs = As + ASZ;
        {
            const int kb = lk4 * 4;
            As[(kb + 0) * 68 + lrow]      = a0.x;
            As[(kb + 1) * 68 + lrow]      = a0.y;
            As[(kb + 2) * 68 + lrow]      = a0.z;
            As[(kb + 3) * 68 + lrow]      = a0.w;
            As[(kb + 0) * 68 + 32 + lrow] = a1.x;
            As[(kb + 1) * 68 + 32 + lrow] = a1.y;
            As[(kb + 2) * 68 + 32 + lrow] = a1.z;
            As[(kb + 3) * 68 + 32 + lrow] = a1.w;
            Bs[(kb + 0) * 33 + lrow] = wv.x;
            Bs[(kb + 1) * 33 + lrow] = wv.y;
            Bs[(kb + 2) * 33 + lrow] = wv.z;
            Bs[(kb + 3) * 33 + lrow] = wv.w;
        }
        __syncthreads();

        // prefetch next tile (redundant reload on last iter — harmless)
        {
            const int ktn = (kt < KT - 1) ? (kt + 1) : kt;
            const int k0  = ktn * 32;
            const float* Ap = (k0 < 512) ? A0 : A1;
            const int kl    = k0 & 511;
            a0 = *reinterpret_cast<const float4*>(Ap + (size_t)(m0      + lrow) * 512 + kl + lk4 * 4);
            a1 = *reinterpret_cast<const float4*>(Ap + (size_t)(m0 + 32 + lrow) * 512 + kl + lk4 * 4);
            wv = Wp[(size_t)ktn * 8];
        }

        const float* Ab = As + tm * 8;
        const float* Bb = Bs + ln;
        #pragma unroll
        for (int kk = 0; kk < 32; ++kk) {
            const ulonglong2 aA = *reinterpret_cast<const ulonglong2*>(Ab + kk * 68);
            const ulonglong2 aB = *reinterpret_cast<const ulonglong2*>(Ab + kk * 68 + 4);
            const unsigned int bu = __float_as_uint(Bb[kk * 33]);
            unsigned long long bb;
            asm("mov.b64 %0, {%1, %1};" : "=l"(bb) : "r"(bu));
            asm("fma.rn.f32x2 %0, %1, %2, %0;" : "+l"(acc[0]) : "l"(aA.x), "l"(bb));
            asm("fma.rn.f32x2 %0, %1, %2, %0;" : "+l"(acc[1]) : "l"(aA.y), "l"(bb));
            asm("fma.rn.f32x2 %0, %1, %2, %0;" : "+l"(acc[2]) : "l"(aB.x), "l"(bb));
            asm("fma.rn.f32x2 %0, %1, %2, %0;" : "+l"(acc[3]) : "l"(aB.y), "l"(bb));
        }
    }
}

// ---------------- persistent kernel: whole network in one launch ----------------
__global__ __launch_bounds__(256, 1)
void nested_lstm_persistent(const float* __restrict__ x,
                            const float* __restrict__ h0,
                            const float* __restrict__ Wg,
                            const float* __restrict__ bg,
                            const float* __restrict__ Wi,
                            const float* __restrict__ bi,
                            float* __restrict__ out)
{
    __shared__ float smem[2 * BUFSZ];
    float* sG = smem;                        // epilogue reuse of buf0 As: [64][33] = 2112 <= 2176

    const int tid  = threadIdx.x;
    const int cta  = blockIdx.x;             // 0..127
    const int m0   = (cta & 1) * 64;
    const int j0   = (cta >> 1) * 8;
    const int tm   = tid >> 5;               // warp id 0..7 -> rows m0 + tm*8 ..
    const int ln   = tid & 31;               // lane -> output column 0..31
    const int lrow = tid >> 3;               // loader mapping (unchanged)
    const int lk4  = tid & 7;
    const int gtid = cta * 256 + tid;

    // weight row for column c: gate c>>3, j = j0 + (c&7)
    const int wrow_ld = ((lrow >> 3) * HH) + j0 + (lrow & 7);   // loader's column
    const int wr_my   = ((ln   >> 3) * HH) + j0 + (ln   & 7);   // this thread's column

    unsigned int epoch = 0;

    for (int l = 0; l < LL; ++l) {
        // ---- init recurrent state for this layer ----
        {
            const float* p = h0 + (size_t)l * 4 * BHN;
            for (int i = gtid; i < BHN; i += NCTA * 256) {
                d_h[i]     = p[i];
                d_c[i]     = p[BHN + i];
                d_hi[0][i] = p[2 * BHN + i];
                d_ci[i]    = p[3 * BHN + i];
            }
        }
        const float* Wgl = Wg + (size_t)l * NG * KDIM;
        const float* bgl = bg + (size_t)l * NG;
        const float* Wil = Wi + (size_t)l * NG * KDIM;
        const float* bil = bi + (size_t)l * NG;
        const float* Ain = (l == 0) ? x : d_y0;     // both row-stride 512
        float*       yo  = (l == 0) ? d_y0 : out;

        gsync(epoch);   // state init visible; prev layer's d_y0 complete

        // ---- Phase A (parallel over t): Z[t] = Ain_t @ Wgx^T + bg ----
        for (int t = 0; t < TT; ++t) {
            unsigned long long acc[4] = {0ull, 0ull, 0ull, 0ull};
            gemm_tile<16>(Ain + (size_t)t * BB * 512, (const float*)0, Wgl,
                          smem, m0, wrow_ld, lrow, lk4, tm, ln, acc);
            float* Zt = d_Z + (size_t)t * BB * NG;
            const float bval = bgl[wr_my];
            #pragma unroll
            for (int p = 0; p < 4; ++p) {
                const float2 v = unpack64(acc[p]);
                const int row = tm * 8 + 2 * p;
                Zt[(size_t)(m0 + row    ) * NG + wr_my] = v.x + bval;
                Zt[(size_t)(m0 + row + 1) * NG + wr_my] = v.y + bval;
            }
            __syncthreads();   // Z stores done per-thread; guard smem reuse across gemms
        }
        gsync(epoch);

        // ---- Sequential recurrence ----
        const float* Whl = Wgl + 512;   // h-columns of Wg rows
        for (int t = 0; t < TT; ++t) {
            const int par = t & 1;

            // outer: gates = h @ Wgh^T + Z[t]
            {
                unsigned long long acc[4] = {0ull, 0ull, 0ull, 0ull};
                gemm_tile<16>(d_h, (const float*)0, Whl,
                              smem, m0, wrow_ld, lrow, lk4, tm, ln, acc);
                const float* Zt = d_Z + (size_t)t * BB * NG;
                #pragma unroll
                for (int p = 0; p < 4; ++p) {
                    const float2 v = unpack64(acc[p]);
                    const int row = tm * 8 + 2 * p;
                    sG[(row    ) * 33 + ln] = v.x + Zt[(size_t)(m0 + row    ) * NG + wr_my];
                    sG[(row + 1) * 33 + ln] = v.y + Zt[(size_t)(m0 + row + 1) * NG + wr_my];
                }
                __syncthreads();
                for (int e = tid; e < 64 * 8; e += 256) {
                    const int jj  = e & 7;
                    const int row = e >> 3;
                    const int idx = (m0 + row) * HH + j0 + jj;
                    const float gi = sG[row * 33 + jj];
                    const float gf = sG[row * 33 +  8 + jj];
                    const float go = sG[row * 33 + 16 + jj];
                    const float gc = sG[row * 33 + 24 + jj];
                    d_cell[idx] = sigmf(gf) * d_c[idx] + sigmf(gi) * tanhf(gc);
                    d_sigo[idx] = sigmf(go);
                }
            }
            gsync(epoch);   // d_cell/d_sigo complete before inner GEMM reads them

            // inner: gates2 = [cell, hi] @ Wi^T + bi
            {
                unsigned long long acc[4] = {0ull, 0ull, 0ull, 0ull};
                gemm_tile<32>(d_cell, d_hi[par], Wil,
                              smem, m0, wrow_ld, lrow, lk4, tm, ln, acc);
                const float bval = bil[wr_my];
                #pragma unroll
                for (int p = 0; p < 4; ++p) {
                    const float2 v = unpack64(acc[p]);
                    const int row = tm * 8 + 2 * p;
                    sG[(row    ) * 33 + ln] = v.x + bval;
                    sG[(row + 1) * 33 + ln] = v.y + bval;
                }
                __syncthreads();
                for (int e = tid; e < 64 * 8; e += 256) {
                    const int jj  = e & 7;
                    const int row = e >> 3;
                    const int idx = (m0 + row) * HH + j0 + jj;
                    const float gi = sG[row * 33 + jj];
                    const float gf = sG[row * 33 +  8 + jj];
                    const float go = sG[row * 33 + 16 + jj];
                    const float gc = sG[row * 33 + 24 + jj];
                    const float cin = sigmf(gf) * d_ci[idx] + sigmf(gi) * tanhf(gc);
                    const float hin = sigmf(go) * tanhf(cin);
                    const float hn  = d_sigo[idx] * tanhf(hin);
                    d_ci[idx]          = cin;
                    d_hi[par ^ 1][idx] = hin;
                    d_c[idx]           = hin;   // carry: c <- hi_n
                    d_h[idx]           = hn;
                    yo[(size_t)t * BB * HH + idx] = hn;
                }
            }
            gsync(epoch);   // h/c/hi/ci/y complete before next step's outer GEMM
        }
    }
}

extern "C" void kernel_launch(void* const* d_in, const int* in_sizes, int n_in,
                              void* d_out, int out_size)
{
    const float* x  = (const float*)d_in[0];   // (T,B,C)
    const float* h0 = (const float*)d_in[1];   // (L,4,B,H)
    const float* Wg = (const float*)d_in[2];   // (L,4H,C+H)
    const float* bg = (const float*)d_in[3];   // (L,4H)
    const float* Wi = (const float*)d_in[4];   // (L,4H,2H)
    const float* bi = (const float*)d_in[5];   // (L,4H)
    float* out = (float*)d_out;                // (T,B,H) f32

    reset_bar_kernel<<<1, 1>>>();
    nested_lstm_persistent<<<NCTA, 256>>>(x, h0, Wg, bg, Wi, bi, out);
}

// round 11
// speedup vs baseline: 1.0051x; 1.0051x over previous
#include <cuda_runtime.h>
#include <math.h>

// Problem constants (fixed by the reference)
#define TT   256
#define BB   128
#define CC   512
#define HH   512
#define LL   2
#define KDIM 1024          // C+H == 2H
#define NG   2048          // 4H
#define BHN  (BB*HH)       // 65536
#define NCTA 128           // persistent grid (<= 148 SMs -> all co-resident)
#define NTHREADS 512       // 2 k-groups x 256

// per-group smem buffer: As[32][68] (2176) + Bs[32][33] (1056) = 3232 floats
#define ASZ   2176
#define BUFSZ 3232

// ---------------- scratch (static __device__, no allocations) ----------------
__device__ float d_y0[(size_t)TT*BB*HH];  // layer-0 output (64 MB)
__device__ float d_Z [(size_t)TT*NCTA*64*32]; // x-part of outer gates (+bias), blocked [t][cta][row][col]
__device__ float d_h[BHN];                // outer hidden
__device__ float d_c[BHN];                // outer cell state
__device__ float d_hi[2][BHN];            // inner hidden (ping-pong)
__device__ float d_ci[BHN];               // inner cell state
__device__ float d_cell[BHN];             // outer candidate cell (input to inner GEMM)
__device__ float d_sigo[BHN];             // sigmoid(outer o-gate)
__device__ unsigned int g_bar;            // grid barrier counter (reset per launch)

__device__ __forceinline__ float sigmf(float x) { return 1.0f / (1.0f + expf(-x)); }

__global__ void reset_bar_kernel() { g_bar = 0u; }

// Software grid barrier: all NCTA CTAs co-resident; monotonic counter.
__device__ __forceinline__ void gsync(unsigned int& epoch)
{
    ++epoch;
    __syncthreads();
    if (threadIdx.x == 0) {
        __threadfence();
        atomicAdd(&g_bar, 1u);
        const unsigned int target = epoch * (unsigned int)NCTA;
        while (*(volatile unsigned int*)&g_bar < target) { }
        __threadfence();
    }
    __syncthreads();
}

// named barrier over one 256-thread k-group
__device__ __forceinline__ void kbar(int id)
{
    asm volatile("bar.sync %0, %1;" :: "r"(id), "r"(256) : "memory");
}

__device__ __forceinline__ float2 unpack64(unsigned long long v)
{
    float2 r;
    asm("mov.b64 {%0, %1}, %2;" : "=f"(r.x), "=f"(r.y) : "l"(v));
    return r;
}

__device__ __forceinline__ unsigned long long addf32x2(unsigned long long a, unsigned long long b)
{
    unsigned long long r;
    asm("add.rn.f32x2 %0, %1, %2;" : "=l"(r) : "l"(a), "l"(b));
    return r;
}

// ---------------- GEMM tile, one k-group ----------------
// out[b, n] = sum over this group's k-tiles of A[b,k] * W[n,k].
// CTA tile 64 rows (m0) x 32 cols (4 gates x 8 j at j0). Per group (256 thr):
//   warp tm = 0..7 owns rows m0 + tm*8 .. +7  (A reads = warp-broadcast LDS.128)
//   lane ln owns one output column            (B read  = conflict-free LDS.32)
// acc[p] = f32x2 for rows (tm*8+2p, +1). Group kg does tiles kt = kg, kg+2, ...
template<int KT>
__device__ __forceinline__ void gemm_tile_kg(const float* __restrict__ A0,
                                             const float* __restrict__ A1,
                                             const float* __restrict__ W,
                                             float* buf,
                                             int m0, int wrow, int lrow, int lk4,
                                             int tm, int ln, int kg,
                                             unsigned long long acc[4])
{
    float* As = buf;
    float* Bs = buf + ASZ;
    const float4* Wp = reinterpret_cast<const float4*>(W + (size_t)wrow * KDIM) + lk4;
    const int barid = kg + 1;

    // prologue: tile kg (k0 = kg*32 < 512 -> A0 half)
    float4 a0 = *reinterpret_cast<const float4*>(A0 + (size_t)(m0      + lrow) * 512 + kg * 32 + lk4 * 4);
    float4 a1 = *reinterpret_cast<const float4*>(A0 + (size_t)(m0 + 32 + lrow) * 512 + kg * 32 + lk4 * 4);
    float4 wv = Wp[(size_t)kg * 8];

    #pragma unroll 1
    for (int kt = kg; kt < KT; kt += 2) {
        kbar(barid);                 // this group's readers of prev tile done
        {
            const int kb = lk4 * 4;
            As[(kb + 0) * 68 + lrow]      = a0.x;
            As[(kb + 1) * 68 + lrow]      = a0.y;
            As[(kb + 2) * 68 + lrow]      = a0.z;
            As[(kb + 3) * 68 + lrow]      = a0.w;
            As[(kb + 0) * 68 + 32 + lrow] = a1.x;
            As[(kb + 1) * 68 + 32 + lrow] = a1.y;
            As[(kb + 2) * 68 + 32 + lrow] = a1.z;
            As[(kb + 3) * 68 + 32 + lrow] = a1.w;
            Bs[(kb + 0) * 33 + lrow] = wv.x;
            Bs[(kb + 1) * 33 + lrow] = wv.y;
            Bs[(kb + 2) * 33 + lrow] = wv.z;
            Bs[(kb + 3) * 33 + lrow] = wv.w;
        }
        kbar(barid);                 // data ready

        // prefetch this group's next tile (redundant reload on last iter — harmless)
        {
            const int ktn = (kt + 2 < KT) ? (kt + 2) : kt;
            const int k0  = ktn * 32;
            const float* Ap = (k0 < 512) ? A0 : A1;
            const int kl    = k0 & 511;
            a0 = *reinterpret_cast<const float4*>(Ap + (size_t)(m0      + lrow) * 512 + kl + lk4 * 4);
            a1 = *reinterpret_cast<const float4*>(Ap + (size_t)(m0 + 32 + lrow) * 512 + kl + lk4 * 4);
            wv = Wp[(size_t)ktn * 8];
        }

        const float* Ab = As + tm * 8;
        const float* Bb = Bs + ln;
        #pragma unroll
        for (int kk = 0; kk < 32; ++kk) {
            const ulonglong2 aA = *reinterpret_cast<const ulonglong2*>(Ab + kk * 68);
            const ulonglong2 aB = *reinterpret_cast<const ulonglong2*>(Ab + kk * 68 + 4);
            const unsigned int bu = __float_as_uint(Bb[kk * 33]);
            unsigned long long bb;
            asm("mov.b64 %0, {%1, %1};" : "=l"(bb) : "r"(bu));
            asm("fma.rn.f32x2 %0, %1, %2, %0;" : "+l"(acc[0]) : "l"(aA.x), "l"(bb));
            asm("fma.rn.f32x2 %0, %1, %2, %0;" : "+l"(acc[1]) : "l"(aA.y), "l"(bb));
            asm("fma.rn.f32x2 %0, %1, %2, %0;" : "+l"(acc[2]) : "l"(aB.x), "l"(bb));
            asm("fma.rn.f32x2 %0, %1, %2, %0;" : "+l"(acc[3]) : "l"(aB.y), "l"(bb));
        }
    }
}

// ---------------- persistent kernel: whole network in one launch ----------------
__global__ __launch_bounds__(NTHREADS, 1)
void nested_lstm_persistent(const float* __restrict__ x,
                            const float* __restrict__ h0,
                            const float* __restrict__ Wg,
                            const float* __restrict__ bg,
                            const float* __restrict__ Wi,
                            const float* __restrict__ bi,
                            float* __restrict__ out)
{
    __shared__ __align__(16) float smem[2 * BUFSZ];
    float* sG = smem;                 // epilogue gates: [64][33] = 2112, in buffer0 As area
    unsigned long long* red = reinterpret_cast<unsigned long long*>(smem + BUFSZ); // kg1 buffer

    const int tid  = threadIdx.x;
    const int cta  = blockIdx.x;      // 0..127
    const int kg   = tid >> 8;        // k-group 0/1
    const int t128 = tid & 255;
    const int m0   = (cta & 1) * 64;
    const int j0   = (cta >> 1) * 8;
    const int tm   = t128 >> 5;       // warp-in-group 0..7 -> rows m0 + tm*8 ..
    const int ln   = t128 & 31;       // lane -> output column 0..31
    const int lrow = t128 >> 3;       // loader mapping
    const int lk4  = t128 & 7;
    const int gtid = cta * NTHREADS + tid;
    float* buf = smem + kg * BUFSZ;

    // weight row for column c: gate c>>3, j = j0 + (c&7)
    const int wrow_ld = ((lrow >> 3) * HH) + j0 + (lrow & 7);
    const int wr_my   = ((ln   >> 3) * HH) + j0 + (ln   & 7);

    unsigned int epoch = 0;

    for (int l = 0; l < LL; ++l) {
        // ---- init recurrent state for this layer ----
        {
            const float* p = h0 + (size_t)l * 4 * BHN;
            for (int i = gtid; i < BHN; i += NCTA * NTHREADS) {
                d_h[i]     = p[i];
                d_c[i]     = p[BHN + i];
                d_hi[0][i] = p[2 * BHN + i];
                d_ci[i]    = p[3 * BHN + i];
            }
        }
        const float* Wgl = Wg + (size_t)l * NG * KDIM;
        const float* bgl = bg + (size_t)l * NG;
        const float* Wil = Wi + (size_t)l * NG * KDIM;
        const float* bil = bi + (size_t)l * NG;
        const float* Ain = (l == 0) ? x : d_y0;     // both row-stride 512
        float*       yo  = (l == 0) ? d_y0 : out;

        gsync(epoch);   // state init visible; prev layer's d_y0 complete

        // ---- Phase A (parallel over t): Z[t] = Ain_t @ Wgx^T + bg ----
        for (int t = 0; t < TT; ++t) {
            unsigned long long acc[4] = {0ull, 0ull, 0ull, 0ull};
            gemm_tile_kg<16>(Ain + (size_t)t * BB * 512, (const float*)0, Wgl,
                             buf, m0, wrow_ld, lrow, lk4, tm, ln, kg, acc);
            __syncthreads();
            if (kg == 1) {
                #pragma unroll
                for (int p = 0; p < 4; ++p) red[(tm * 4 + p) * 32 + ln] = acc[p];
            }
            __syncthreads();
            if (kg == 0) {
                float* Zt = d_Z + (size_t)(t * NCTA + cta) * 2048;
                const float bval = bgl[wr_my];
                #pragma unroll
                for (int p = 0; p < 4; ++p) {
                    const float2 v = unpack64(addf32x2(acc[p], red[(tm * 4 + p) * 32 + ln]));
                    const int row = tm * 8 + 2 * p;
                    Zt[(row    ) * 32 + ln] = v.x + bval;
                    Zt[(row + 1) * 32 + ln] = v.y + bval;
                }
            }
            __syncthreads();   // red consumed before kg1 re-stages buffer1
        }
        gsync(epoch);

        // ---- Sequential recurrence ----
        const float* Whl = Wgl + 512;   // h-columns of Wg rows
        for (int t = 0; t < TT; ++t) {
            const int par = t & 1;

            // outer: gates = h @ Wgh^T + Z[t]
            {
                unsigned long long acc[4] = {0ull, 0ull, 0ull, 0ull};
                gemm_tile_kg<16>(d_h, (const float*)0, Whl,
                                 buf, m0, wrow_ld, lrow, lk4, tm, ln, kg, acc);
                __syncthreads();
                if (kg == 1) {
                    #pragma unroll
                    for (int p = 0; p < 4; ++p) red[(tm * 4 + p) * 32 + ln] = acc[p];
                }
                __syncthreads();
                if (kg == 0) {
                    const float* Zt = d_Z + (size_t)(t * NCTA + cta) * 2048;
                    #pragma unroll
                    for (int p = 0; p < 4; ++p) {
                        const float2 v = unpack64(addf32x2(acc[p], red[(tm * 4 + p) * 32 + ln]));
                        const int row = tm * 8 + 2 * p;
                        sG[(row    ) * 33 + ln] = v.x + Zt[(row    ) * 32 + ln];
                        sG[(row + 1) * 33 + ln] = v.y + Zt[(row + 1) * 32 + ln];
                    }
                }
                __syncthreads();
                {   // 512 threads, one gate element each
                    const int jj  = tid & 7;
                    const int row = tid >> 3;
                    const int idx = (m0 + row) * HH + j0 + jj;
                    const float gi = sG[row * 33 + jj];
                    const float gf = sG[row * 33 +  8 + jj];
                    const float go = sG[row * 33 + 16 + jj];
                    const float gc = sG[row * 33 + 24 + jj];
                    d_cell[idx] = sigmf(gf) * d_c[idx] + sigmf(gi) * tanhf(gc);
                    d_sigo[idx] = sigmf(go);
                }
            }
            gsync(epoch);   // d_cell/d_sigo complete before inner GEMM reads them

            // inner: gates2 = [cell, hi] @ Wi^T + bi
            {
                unsigned long long acc[4] = {0ull, 0ull, 0ull, 0ull};
                gemm_tile_kg<32>(d_cell, d_hi[par], Wil,
                                 buf, m0, wrow_ld, lrow, lk4, tm, ln, kg, acc);
                __syncthreads();
                if (kg == 1) {
                    #pragma unroll
                    for (int p = 0; p < 4; ++p) red[(tm * 4 + p) * 32 + ln] = acc[p];
                }
                __syncthreads();
                if (kg == 0) {
                    const float bval = bil[wr_my];
                    #pragma unroll
                    for (int p = 0; p < 4; ++p) {
                        const float2 v = unpack64(addf32x2(acc[p], red[(tm * 4 + p) * 32 + ln]));
                        const int row = tm * 8 + 2 * p;
                        sG[(row    ) * 33 + ln] = v.x + bval;
                        sG[(row + 1) * 33 + ln] = v.y + bval;
                    }
                }
                __syncthreads();
                {   // 512 threads, one element each
                    const int jj  = tid & 7;
                    const int row = tid >> 3;
                    const int idx = (m0 + row) * HH + j0 + jj;
                    const float gi = sG[row * 33 + jj];
                    const float gf = sG[row * 33 +  8 + jj];
                    const float go = sG[row * 33 + 16 + jj];
                    const float gc = sG[row * 33 + 24 + jj];
                    const float cin = sigmf(gf) * d_ci[idx] + sigmf(gi) * tanhf(gc);
                    const float hin = sigmf(go) * tanhf(cin);
                    const float hn  = d_sigo[idx] * tanhf(hin);
                    d_ci[idx]          = cin;
                    d_hi[par ^ 1][idx] = hin;
                    d_c[idx]           = hin;   // carry: c <- hi_n
                    d_h[idx]           = hn;
                    yo[(size_t)t * BB * HH + idx] = hn;
                }
            }
            gsync(epoch);   // h/c/hi/ci/y complete before next step's outer GEMM
        }
    }
}

extern "C" void kernel_launch(void* const* d_in, const int* in_sizes, int n_in,
                              void* d_out, int out_size)
{
    const float* x  = (const float*)d_in[0];   // (T,B,C)
    const float* h0 = (const float*)d_in[1];   // (L,4,B,H)
    const float* Wg = (const float*)d_in[2];   // (L,4H,C+H)
    const float* bg = (const float*)d_in[3];   // (L,4H)
    const float* Wi = (const float*)d_in[4];   // (L,4H,2H)
    const float* bi = (const float*)d_in[5];   // (L,4H)
    float* out = (float*)d_out;                // (T,B,H) f32

    reset_bar_kernel<<<1, 1>>>();
    nested_lstm_persistent<<<NCTA, NTHREADS>>>(x, h0, Wg, bg, Wi, bi, out);
}

// round 14
// speedup vs baseline: 2.3169x; 2.3052x over previous
#include <cuda_runtime.h>
#include <cuda_bf16.h>
#include <math.h>
#include <stdint.h>

// Problem constants (fixed by the reference)
#define TT 256
#define BB 128
#define CC 512
#define HH 512
#define LL 2
#define BHN (BB*HH)          // 65536
#define NCTA 128             // persistent grid, all co-resident
#define NTH 256              // 8 warps

// smem buffer layout (bytes). Row pitch 144B = 72 halves -> conflict-free ldmatrix.
#define OFF_AHI 0
#define OFF_ALO 9216                 // 64 rows * 144
#define OFF_BHI 18432
#define OFF_BLO 23040                // +32*144
#define BUFSZ   27648
#define SMEM_DYN (2*BUFSZ + 1024)

typedef __nv_bfloat16 bf16;

// ---------------- scratch (static __device__, no allocations) ----------------
__device__ bf16 d_xhi [(size_t)TT*BB*CC];     // split input x
__device__ bf16 d_xlo [(size_t)TT*BB*CC];
__device__ bf16 d_y0hi[(size_t)TT*BB*HH];     // split layer-0 output
__device__ bf16 d_y0lo[(size_t)TT*BB*HH];
__device__ bf16 d_Wxhi[(size_t)LL*2048*512];  // Wg x-columns  [l][n][k]
__device__ bf16 d_Wxlo[(size_t)LL*2048*512];
__device__ bf16 d_Whhi[(size_t)LL*2048*512];  // Wg h-columns  [l][n][k]
__device__ bf16 d_Whlo[(size_t)LL*2048*512];
__device__ bf16 d_Wihi[(size_t)LL*2048*1024]; // Wi            [l][n][k]
__device__ bf16 d_Wilo[(size_t)LL*2048*1024];
__device__ float d_Z[(size_t)TT*NCTA*2048];   // x-part of outer gates (+bg), [t][cta][64][32]
__device__ bf16 d_hhi[BHN],    d_hlo[BHN];    // outer hidden planes
__device__ bf16 d_cellhi[BHN], d_celllo[BHN]; // outer candidate cell planes
__device__ bf16 d_hihi[2][BHN], d_hilo[2][BHN]; // inner hidden ping-pong planes
__device__ float d_c[BHN];                    // outer cell state (fp32)
__device__ float d_ci[BHN];                   // inner cell state (fp32)
__device__ float d_sigo[BHN];                 // sigmoid(outer o-gate)
__device__ unsigned int g_bar;

__device__ __forceinline__ float sigmf(float x) { return 1.0f / (1.0f + expf(-x)); }

__device__ __forceinline__ void split2(float v, bf16& h, bf16& l)
{
    h = __float2bfloat16(v);
    l = __float2bfloat16(v - __bfloat162float(h));
}

__global__ void reset_bar_kernel() { g_bar = 0u; }

__device__ __forceinline__ void gsync(unsigned int& epoch)
{
    ++epoch;
    __syncthreads();
    if (threadIdx.x == 0) {
        __threadfence();
        atomicAdd(&g_bar, 1u);
        const unsigned int target = epoch * (unsigned int)NCTA;
        while (*(volatile unsigned int*)&g_bar < target) { }
        __threadfence();
    }
    __syncthreads();
}

__device__ __forceinline__ uint32_t smem_u32(const void* p)
{
    uint32_t a;
    asm("{ .reg .u64 t; cvta.to.shared.u64 t, %1; cvt.u32.u64 %0, t; }" : "=r"(a) : "l"(p));
    return a;
}

#define LDSM4(r, addr) \
    asm volatile("ldmatrix.sync.aligned.m8n8.x4.shared.b16 {%0,%1,%2,%3}, [%4];" \
        : "=r"((r)[0]), "=r"((r)[1]), "=r"((r)[2]), "=r"((r)[3]) : "r"(addr))

#define MMA16816(d, a, b0, b1) \
    asm volatile("mma.sync.aligned.m16n8k16.row.col.f32.bf16.bf16.f32 " \
        "{%0,%1,%2,%3}, {%4,%5,%6,%7}, {%8,%9}, {%0,%1,%2,%3};" \
        : "+f"((d)[0]), "+f"((d)[1]), "+f"((d)[2]), "+f"((d)[3]) \
        : "r"((a)[0]), "r"((a)[1]), "r"((a)[2]), "r"((a)[3]), "r"(b0), "r"(b1))

// ---------------- staging loads (global -> regs) ----------------
// A tile: 64 rows x 64 k-halves per plane. Row stride 512 halves = 64 uint4.
__device__ __forceinline__ void lda(const bf16* Ah, const bf16* Al, int c_eff, int tid,
                                    uint4* pah, uint4* pal)
{
    const uint4* gh = (const uint4*)Ah;
    const uint4* gl = (const uint4*)Al;
    #pragma unroll
    for (int i = 0; i < 2; ++i) {
        const int u = tid + i * 256;
        const int row = u >> 3, q = u & 7;
        const int gi = row * 64 + c_eff * 8 + q;
        pah[i] = gh[gi];
        pal[i] = gl[gi];
    }
}

// B tile: 32 cols x 64 k-halves per plane. col c -> weight row ((c>>3)<<9)+j0+(c&7).
__device__ __forceinline__ void ldb(const bf16* Bh, const bf16* Bl, int c, int strideB4,
                                    int j0, int tid, uint4& pbh, uint4& pbl)
{
    const int col = tid >> 3, q = tid & 7;
    const int wr = ((col >> 3) << 9) + j0 + (col & 7);
    const int gi = wr * strideB4 + c * 8 + q;
    pbh = ((const uint4*)Bh)[gi];
    pbl = ((const uint4*)Bl)[gi];
}

// ---------------- split-bf16 HMMA GEMM: D[64x32] = A[64xK] @ W[32 x K]^T ----------------
// acc[3][2][4]: term (hh,lh,hl) x n8-tile x frag. K chunks of 64; A switches source at sc.
__device__ void run_gemm(unsigned char* smp, uint32_t smp_u,
                         const bf16* A0h, const bf16* A0l,
                         const bf16* A1h, const bf16* A1l,
                         const bf16* Bh,  const bf16* Bl,
                         int strideB4, int nchunks, int sc, int j0, int tid,
                         uint32_t aoff, uint32_t boff,
                         float acc[3][2][4])
{
    #pragma unroll
    for (int s = 0; s < 3; ++s)
        #pragma unroll
        for (int t = 0; t < 2; ++t)
            #pragma unroll
            for (int i = 0; i < 4; ++i) acc[s][t][i] = 0.0f;

    uint4 pah[2], pal[2], pbh, pbl;
    lda(A0h, A0l, 0, tid, pah, pal);
    ldb(Bh, Bl, 0, strideB4, j0, tid, pbh, pbl);

    #pragma unroll 1
    for (int c = 0; c < nchunks; ++c) {
        unsigned char* buf = smp + (c & 1) * BUFSZ;
        #pragma unroll
        for (int i = 0; i < 2; ++i) {
            const int u = tid + i * 256;
            const int row = u >> 3, q = u & 7;
            *(uint4*)(buf + OFF_AHI + row * 144 + q * 16) = pah[i];
            *(uint4*)(buf + OFF_ALO + row * 144 + q * 16) = pal[i];
        }
        {
            const int col = tid >> 3, q = tid & 7;
            *(uint4*)(buf + OFF_BHI + col * 144 + q * 16) = pbh;
            *(uint4*)(buf + OFF_BLO + col * 144 + q * 16) = pbl;
        }
        // prefetch next chunk while this one is consumed
        if (c + 1 < nchunks) {
            const int cn = c + 1;
            if (cn < sc) lda(A0h, A0l, cn, tid, pah, pal);
            else         lda(A1h, A1l, cn - sc, tid, pah, pal);
            ldb(Bh, Bl, cn, strideB4, j0, tid, pbh, pbl);
        }
        __syncthreads();

        const uint32_t bu = smp_u + (c & 1) * BUFSZ;
        #pragma unroll
        for (int k16 = 0; k16 < 4; ++k16) {
            uint32_t ah[4], al[4], bh[4], bl[4];
            LDSM4(ah, bu + OFF_AHI + aoff + k16 * 32);
            LDSM4(al, bu + OFF_ALO + aoff + k16 * 32);
            LDSM4(bh, bu + OFF_BHI + boff + k16 * 32);
            LDSM4(bl, bu + OFF_BLO + boff + k16 * 32);
            MMA16816(acc[0][0], ah, bh[0], bh[1]);
            MMA16816(acc[0][1], ah, bh[2], bh[3]);
            MMA16816(acc[1][0], al, bh[0], bh[1]);
            MMA16816(acc[1][1], al, bh[2], bh[3]);
            MMA16816(acc[2][0], ah, bl[0], bl[1]);
            MMA16816(acc[2][1], ah, bl[2], bl[3]);
        }
    }
}

// ---------------- persistent kernel ----------------
__global__ __launch_bounds__(NTH, 1)
void nested_lstm_persistent(const float* __restrict__ x,
                            const float* __restrict__ h0,
                            const float* __restrict__ Wg,
                            const float* __restrict__ bg,
                            const float* __restrict__ Wi,
                            const float* __restrict__ bi,
                            float* __restrict__ out)
{
    extern __shared__ __align__(16) unsigned char dsm[];

    const int tid  = threadIdx.x;
    const int cta  = blockIdx.x;           // 0..127
    const int m0   = (cta & 1) * 64;
    const int j0   = (cta >> 1) * 8;
    const int lane = tid & 31;
    const int w    = tid >> 5;
    const int wm   = w >> 1;               // row group: rows m0 + wm*16 .. +15
    const int wn   = w & 1;                // col group: cols wn*16 .. +15
    const int gtid = cta * NTH + tid;
    const int GSTRIDE = NCTA * NTH;

    const uint32_t raw_u = smem_u32(dsm);
    const uint32_t smp_u = (raw_u + 1023u) & ~1023u;
    unsigned char* smp = dsm + (smp_u - raw_u);

    // per-lane ldmatrix offsets within a buffer
    const int ti = lane >> 3;
    const uint32_t aoff = (uint32_t)((wm * 16 + (lane & 7) + (ti & 1) * 8) * 144 + ((ti >> 1) * 8) * 2);
    const uint32_t boff = (uint32_t)((wn * 16 + (lane & 7) + (ti >> 1) * 8) * 144 + ((ti & 1) * 8) * 2);
    // epilogue positions
    const int r_in = lane >> 2;            // 0..7
    const int cq   = lane & 3;

    float* sG = (float*)smp;               // epilogue exchange [64][33] = 8448B, overlays buf0

    unsigned int epoch = 0;

    // ---- Phase 0: split conversions ----
    for (size_t i = gtid; i < (size_t)TT * BB * CC; i += GSTRIDE)
        split2(x[i], d_xhi[i], d_xlo[i]);
    for (size_t i = gtid; i < (size_t)LL * 2048 * 512; i += GSTRIDE) {
        const size_t l2 = i / (2048 * 512), r = i % (2048 * 512);
        const size_t n = r / 512, k = r % 512;
        const size_t src = l2 * 2048 * 1024 + n * 1024 + k;
        split2(Wg[src],       d_Wxhi[i], d_Wxlo[i]);
        split2(Wg[src + 512], d_Whhi[i], d_Whlo[i]);
    }
    for (size_t i = gtid; i < (size_t)LL * 2048 * 1024; i += GSTRIDE)
        split2(Wi[i], d_Wihi[i], d_Wilo[i]);

    for (int l = 0; l < LL; ++l) {
        // ---- init recurrent state ----
        {
            const float* p = h0 + (size_t)l * 4 * BHN;
            for (int i = gtid; i < BHN; i += GSTRIDE) {
                split2(p[i], d_hhi[i], d_hlo[i]);
                d_c[i] = p[BHN + i];
                split2(p[2 * BHN + i], d_hihi[0][i], d_hilo[0][i]);
                d_ci[i] = p[3 * BHN + i];
            }
        }
        const bf16* Axh = ((l == 0) ? d_xhi : d_y0hi) + m0 * 512;
        const bf16* Axl = ((l == 0) ? d_xlo : d_y0lo) + m0 * 512;
        const bf16* Bxh = d_Wxhi + (size_t)l * 2048 * 512;
        const bf16* Bxl = d_Wxlo + (size_t)l * 2048 * 512;
        const bf16* Bhh = d_Whhi + (size_t)l * 2048 * 512;
        const bf16* Bhl = d_Whlo + (size_t)l * 2048 * 512;
        const bf16* Bih = d_Wihi + (size_t)l * 2048 * 1024;
        const bf16* Bil_ = d_Wilo + (size_t)l * 2048 * 1024;
        const float* bgl = bg + (size_t)l * 2048;
        const float* bil = bi + (size_t)l * 2048;

        gsync(epoch);   // conversions + state init visible; prev layer's y0 planes complete

        // ---- Phase A (parallel over t): Z[t] = x_t @ Wx^T + bg ----
        for (int t = 0; t < TT; ++t) {
            float acc[3][2][4];
            run_gemm(smp, smp_u,
                     Axh + (size_t)t * BB * 512, Axl + (size_t)t * BB * 512,
                     Axh, Axl, Bxh, Bxl, 64, 8, 8, j0, tid, aoff, boff, acc);
            float* Zt = d_Z + ((size_t)t * NCTA + cta) * 2048;
            #pragma unroll
            for (int t2 = 0; t2 < 2; ++t2) {
                const int c0  = wn * 16 + t2 * 8 + cq * 2;
                const int wr0 = ((c0 >> 3) << 9) + j0 + (c0 & 7);
                const float b0v = bgl[wr0], b1v = bgl[wr0 + 1];
                const int r0 = wm * 16 + r_in;
                Zt[(r0    ) * 32 + c0    ] = acc[0][t2][0] + acc[1][t2][0] + acc[2][t2][0] + b0v;
                Zt[(r0    ) * 32 + c0 + 1] = acc[0][t2][1] + acc[1][t2][1] + acc[2][t2][1] + b1v;
                Zt[(r0 + 8) * 32 + c0    ] = acc[0][t2][2] + acc[1][t2][2] + acc[2][t2][2] + b0v;
                Zt[(r0 + 8) * 32 + c0 + 1] = acc[0][t2][3] + acc[1][t2][3] + acc[2][t2][3] + b1v;
            }
        }
        gsync(epoch);

        // ---- Sequential recurrence ----
        for (int t = 0; t < TT; ++t) {
            const int par = t & 1;

            // outer: gates = h @ Wh^T + Z[t]   (bias already folded into Z)
            {
                float acc[3][2][4];
                run_gemm(smp, smp_u,
                         d_hhi + m0 * 512, d_hlo + m0 * 512,
                         d_hhi, d_hlo, Bhh, Bhl, 64, 8, 8, j0, tid, aoff, boff, acc);
                const float* Zt = d_Z + ((size_t)t * NCTA + cta) * 2048;
                #pragma unroll
                for (int t2 = 0; t2 < 2; ++t2) {
                    const int c0 = wn * 16 + t2 * 8 + cq * 2;
                    const int r0 = wm * 16 + r_in;
                    sG[(r0    ) * 33 + c0    ] = acc[0][t2][0] + acc[1][t2][0] + acc[2][t2][0] + Zt[(r0    ) * 32 + c0    ];
                    sG[(r0    ) * 33 + c0 + 1] = acc[0][t2][1] + acc[1][t2][1] + acc[2][t2][1] + Zt[(r0    ) * 32 + c0 + 1];
                    sG[(r0 + 8) * 33 + c0    ] = acc[0][t2][2] + acc[1][t2][2] + acc[2][t2][2] + Zt[(r0 + 8) * 32 + c0    ];
                    sG[(r0 + 8) * 33 + c0 + 1] = acc[0][t2][3] + acc[1][t2][3] + acc[2][t2][3] + Zt[(r0 + 8) * 32 + c0 + 1];
                }
                __syncthreads();
                for (int e = tid; e < 512; e += NTH) {
                    const int jj  = e & 7;
                    const int row = e >> 3;
                    const int idx = (m0 + row) * HH + j0 + jj;
                    const float gi = sG[row * 33 + jj];
                    const float gf = sG[row * 33 +  8 + jj];
                    const float go = sG[row * 33 + 16 + jj];
                    const float gc = sG[row * 33 + 24 + jj];
                    const float cellv = sigmf(gf) * d_c[idx] + sigmf(gi) * tanhf(gc);
                    split2(cellv, d_cellhi[idx], d_celllo[idx]);
                    d_sigo[idx] = sigmf(go);
                }
            }
            gsync(epoch);   // cell planes + sigo complete before inner GEMM

            // inner: gates2 = [cell, hi] @ Wi^T + bi
            {
                float acc[3][2][4];
                run_gemm(smp, smp_u,
                         d_cellhi + m0 * 512, d_celllo + m0 * 512,
                         d_hihi[par] + m0 * 512, d_hilo[par] + m0 * 512,
                         Bih, Bil_, 128, 16, 8, j0, tid, aoff, boff, acc);
                #pragma unroll
                for (int t2 = 0; t2 < 2; ++t2) {
                    const int c0  = wn * 16 + t2 * 8 + cq * 2;
                    const int wr0 = ((c0 >> 3) << 9) + j0 + (c0 & 7);
                    const float b0v = bil[wr0], b1v = bil[wr0 + 1];
                    const int r0 = wm * 16 + r_in;
                    sG[(r0    ) * 33 + c0    ] = acc[0][t2][0] + acc[1][t2][0] + acc[2][t2][0] + b0v;
                    sG[(r0    ) * 33 + c0 + 1] = acc[0][t2][1] + acc[1][t2][1] + acc[2][t2][1] + b1v;
                    sG[(r0 + 8) * 33 + c0    ] = acc[0][t2][2] + acc[1][t2][2] + acc[2][t2][2] + b0v;
                    sG[(r0 + 8) * 33 + c0 + 1] = acc[0][t2][3] + acc[1][t2][3] + acc[2][t2][3] + b1v;
                }
                __syncthreads();
                for (int e = tid; e < 512; e += NTH) {
                    const int jj  = e & 7;
                    const int row = e >> 3;
                    const int idx = (m0 + row) * HH + j0 + jj;
                    const float gi = sG[row * 33 + jj];
                    const float gf = sG[row * 33 +  8 + jj];
                    const float go = sG[row * 33 + 16 + jj];
                    const float gc = sG[row * 33 + 24 + jj];
                    const float cin = sigmf(gf) * d_ci[idx] + sigmf(gi) * tanhf(gc);
                    const float hin = sigmf(go) * tanhf(cin);
                    const float hn  = d_sigo[idx] * tanhf(hin);
                    d_ci[idx] = cin;
                    d_c[idx]  = hin;                           // carry: c <- hi_n
                    split2(hin, d_hihi[par ^ 1][idx], d_hilo[par ^ 1][idx]);
                    split2(hn,  d_hhi[idx], d_hlo[idx]);
                    if (l == 0) {
                        split2(hn, d_y0hi[(size_t)t * BHN + idx], d_y0lo[(size_t)t * BHN + idx]);
                    } else {
                        out[(size_t)t * BHN + idx] = hn;
                    }
                }
            }
            gsync(epoch);   // h/hi/c/ci planes complete before next step
        }
    }
}

extern "C" void kernel_launch(void* const* d_in, const int* in_sizes, int n_in,
                              void* d_out, int out_size)
{
    const float* x  = (const float*)d_in[0];   // (T,B,C)
    const float* h0 = (const float*)d_in[1];   // (L,4,B,H)
    const float* Wg = (const float*)d_in[2];   // (L,4H,C+H)
    const float* bg = (const float*)d_in[3];   // (L,4H)
    const float* Wi = (const float*)d_in[4];   // (L,4H,2H)
    const float* bi = (const float*)d_in[5];   // (L,4H)
    float* out = (float*)d_out;                // (T,B,H) f32

    cudaFuncSetAttribute(nested_lstm_persistent,
                         cudaFuncAttributeMaxDynamicSharedMemorySize, SMEM_DYN);
    reset_bar_kernel<<<1, 1>>>();
    nested_lstm_persistent<<<NCTA, NTH, SMEM_DYN>>>(x, h0, Wg, bg, Wi, bi, out);
}

// round 15
// speedup vs baseline: 2.4809x; 1.0708x over previous
#include <cuda_runtime.h>
#include <cuda_bf16.h>
#include <math.h>
#include <stdint.h>

// Problem constants (fixed by the reference)
#define TT 256
#define BB 128
#define CC 512
#define HH 512
#define LL 2
#define BHN (BB*HH)          // 65536
#define NCTA 128             // persistent grid, all co-resident
#define NTH 512              // 2 k-groups x 8 warps

// per-buffer layout (bytes). Row pitch 144B = 72 halves -> conflict-free ldmatrix.
#define OFF_AHI 0
#define OFF_ALO 9216                 // 64 rows * 144
#define OFF_BHI 18432
#define OFF_BLO 23040                // +32*144
#define BUFSZ   27648
// smem map: [group0 buf0][group0 buf1][group1 buf0][group1 buf1][sG][red]
#define SM_SG   (4*BUFSZ)            // 110592
#define SM_RED  (SM_SG + 8448)       // sG = 64*33*4
#define SMEM_DYN (SM_RED + 8192 + 1024)

typedef __nv_bfloat16 bf16;

// ---------------- scratch (static __device__, no allocations) ----------------
__device__ bf16 d_xhi [(size_t)TT*BB*CC];     // split input x
__device__ bf16 d_xlo [(size_t)TT*BB*CC];
__device__ bf16 d_y0hi[(size_t)TT*BB*HH];     // split layer-0 output
__device__ bf16 d_y0lo[(size_t)TT*BB*HH];
__device__ bf16 d_Wxhi[(size_t)LL*2048*512];  // Wg x-columns  [l][n][k]
__device__ bf16 d_Wxlo[(size_t)LL*2048*512];
__device__ bf16 d_Whhi[(size_t)LL*2048*512];  // Wg h-columns  [l][n][k]
__device__ bf16 d_Whlo[(size_t)LL*2048*512];
__device__ bf16 d_Wihi[(size_t)LL*2048*1024]; // Wi            [l][n][k]
__device__ bf16 d_Wilo[(size_t)LL*2048*1024];
__device__ float d_Z[(size_t)TT*NCTA*2048];   // x-part of outer gates (+bg), [t][cta][64][32]
__device__ bf16 d_hhi[BHN],    d_hlo[BHN];    // outer hidden planes
__device__ bf16 d_cellhi[BHN], d_celllo[BHN]; // outer candidate cell planes
__device__ bf16 d_hihi[2][BHN], d_hilo[2][BHN]; // inner hidden ping-pong planes
__device__ float d_c[BHN];                    // outer cell state (fp32)
__device__ float d_ci[BHN];                   // inner cell state (fp32)
__device__ float d_sigo[BHN];                 // sigmoid(outer o-gate)
__device__ unsigned int g_bar;

__device__ __forceinline__ float sigmf(float x) { return 1.0f / (1.0f + expf(-x)); }

__device__ __forceinline__ void split2(float v, bf16& h, bf16& l)
{
    h = __float2bfloat16(v);
    l = __float2bfloat16(v - __bfloat162float(h));
}

__global__ void reset_bar_kernel() { g_bar = 0u; }

__device__ __forceinline__ void gsync(unsigned int& epoch)
{
    ++epoch;
    __syncthreads();
    if (threadIdx.x == 0) {
        __threadfence();
        atomicAdd(&g_bar, 1u);
        const unsigned int target = epoch * (unsigned int)NCTA;
        while (*(volatile unsigned int*)&g_bar < target) { }
        __threadfence();
    }
    __syncthreads();
}

__device__ __forceinline__ uint32_t smem_u32(const void* p)
{
    uint32_t a;
    asm("{ .reg .u64 t; cvta.to.shared.u64 t, %1; cvt.u32.u64 %0, t; }" : "=r"(a) : "l"(p));
    return a;
}

#define GBAR(id) asm volatile("bar.sync %0, 256;" :: "r"(id) : "memory")

#define LDSM4(r, addr) \
    asm volatile("ldmatrix.sync.aligned.m8n8.x4.shared.b16 {%0,%1,%2,%3}, [%4];" \
        : "=r"((r)[0]), "=r"((r)[1]), "=r"((r)[2]), "=r"((r)[3]) : "r"(addr))

#define MMA16816(d, a, b0, b1) \
    asm volatile("mma.sync.aligned.m16n8k16.row.col.f32.bf16.bf16.f32 " \
        "{%0,%1,%2,%3}, {%4,%5,%6,%7}, {%8,%9}, {%0,%1,%2,%3};" \
        : "+f"((d)[0]), "+f"((d)[1]), "+f"((d)[2]), "+f"((d)[3]) \
        : "r"((a)[0]), "r"((a)[1]), "r"((a)[2]), "r"((a)[3]), "r"(b0), "r"(b1))

// ---------------- staging loads (global -> regs), 256-thread group ----------------
// A tile: 64 rows x 64 k-halves per plane. Row stride 512 halves = 64 uint4.
__device__ __forceinline__ void lda(const bf16* Ah, const bf16* Al, int c_eff, int t128,
                                    uint4* pah, uint4* pal)
{
    const uint4* gh = (const uint4*)Ah;
    const uint4* gl = (const uint4*)Al;
    #pragma unroll
    for (int i = 0; i < 2; ++i) {
        const int u = t128 + i * 256;
        const int row = u >> 3, q = u & 7;
        const int gi = row * 64 + c_eff * 8 + q;
        pah[i] = gh[gi];
        pal[i] = gl[gi];
    }
}

// B tile: 32 cols x 64 k-halves per plane. col c -> weight row ((c>>3)<<9)+j0+(c&7).
__device__ __forceinline__ void ldb(const bf16* Bh, const bf16* Bl, int c, int strideB4,
                                    int j0, int t128, uint4& pbh, uint4& pbl)
{
    const int col = t128 >> 3, q = t128 & 7;
    const int wr = ((col >> 3) << 9) + j0 + (col & 7);
    const int gi = wr * strideB4 + c * 8 + q;
    pbh = ((const uint4*)Bh)[gi];
    pbl = ((const uint4*)Bl)[gi];
}

// ---------------- split-bf16 HMMA GEMM over chunks c = cstart, cstart+cstride, ... < nct ----
// D[64x32] partial = A[64 x (chunks)] @ W[32 x (chunks)]^T, per 256-thread group.
// acc[3][2][4]: term (hh,lh,hl) x n8-tile x frag. A source switches at global chunk sc.
__device__ void run_gemm(unsigned char* gp, uint32_t gp_u,
                         const bf16* A0h, const bf16* A0l,
                         const bf16* A1h, const bf16* A1l,
                         const bf16* Bh,  const bf16* Bl,
                         int strideB4, int cstart, int cstride, int nct, int sc,
                         int j0, int t128, int barid,
                         uint32_t aoff, uint32_t boff,
                         float acc[3][2][4])
{
    #pragma unroll
    for (int s = 0; s < 3; ++s)
        #pragma unroll
        for (int t = 0; t < 2; ++t)
            #pragma unroll
            for (int i = 0; i < 4; ++i) acc[s][t][i] = 0.0f;

    uint4 pah[2], pal[2], pbh, pbl;
    lda(A0h, A0l, cstart, t128, pah, pal);            // cstart < sc always here
    ldb(Bh, Bl, cstart, strideB4, j0, t128, pbh, pbl);

    int ci = 0;
    #pragma unroll 1
    for (int c = cstart; c < nct; c += cstride, ++ci) {
        unsigned char* buf = gp + (ci & 1) * BUFSZ;
        #pragma unroll
        for (int i = 0; i < 2; ++i) {
            const int u = t128 + i * 256;
            const int row = u >> 3, q = u & 7;
            *(uint4*)(buf + OFF_AHI + row * 144 + q * 16) = pah[i];
            *(uint4*)(buf + OFF_ALO + row * 144 + q * 16) = pal[i];
        }
        {
            const int col = t128 >> 3, q = t128 & 7;
            *(uint4*)(buf + OFF_BHI + col * 144 + q * 16) = pbh;
            *(uint4*)(buf + OFF_BLO + col * 144 + q * 16) = pbl;
        }
        // prefetch next chunk while this one is consumed
        const int cn = c + cstride;
        if (cn < nct) {
            if (cn < sc) lda(A0h, A0l, cn, t128, pah, pal);
            else         lda(A1h, A1l, cn - sc, t128, pah, pal);
            ldb(Bh, Bl, cn, strideB4, j0, t128, pbh, pbl);
        }
        GBAR(barid);

        const uint32_t bu = gp_u + (ci & 1) * BUFSZ;
        #pragma unroll
        for (int k16 = 0; k16 < 4; ++k16) {
            uint32_t ah[4], al[4], bh[4], bl[4];
            LDSM4(ah, bu + OFF_AHI + aoff + k16 * 32);
            LDSM4(al, bu + OFF_ALO + aoff + k16 * 32);
            LDSM4(bh, bu + OFF_BHI + boff + k16 * 32);
            LDSM4(bl, bu + OFF_BLO + boff + k16 * 32);
            MMA16816(acc[0][0], ah, bh[0], bh[1]);
            MMA16816(acc[0][1], ah, bh[2], bh[3]);
            MMA16816(acc[1][0], al, bh[0], bh[1]);
            MMA16816(acc[1][1], al, bh[2], bh[3]);
            MMA16816(acc[2][0], ah, bl[0], bl[1]);
            MMA16816(acc[2][1], ah, bl[2], bl[3]);
        }
    }
}

// ---------------- persistent kernel ----------------
__global__ __launch_bounds__(NTH, 1)
void nested_lstm_persistent(const float* __restrict__ x,
                            const float* __restrict__ h0,
                            const float* __restrict__ Wg,
                            const float* __restrict__ bg,
                            const float* __restrict__ Wi,
                            const float* __restrict__ bi,
                            float* __restrict__ out)
{
    extern __shared__ __align__(16) unsigned char dsm[];

    const int tid  = threadIdx.x;
    const int cta  = blockIdx.x;           // 0..127
    const int m0   = (cta & 1) * 64;
    const int j0   = (cta >> 1) * 8;
    const int kg   = tid >> 8;             // k-group 0/1
    const int t128 = tid & 255;
    const int lane = tid & 31;
    const int w    = t128 >> 5;            // warp-in-group 0..7
    const int wm   = w >> 1;               // row group: rows m0 + wm*16 .. +15
    const int wn   = w & 1;                // col group: cols wn*16 .. +15
    const int barid = kg + 1;
    const int gtid = cta * NTH + tid;
    const int GSTRIDE = NCTA * NTH;

    const uint32_t raw_u = smem_u32(dsm);
    const uint32_t smp_u = (raw_u + 1023u) & ~1023u;
    unsigned char* smp = dsm + (smp_u - raw_u);
    unsigned char* gp  = smp + kg * 2 * BUFSZ;     // this group's buffer pair
    const uint32_t gp_u = smp_u + kg * 2 * BUFSZ;
    float* sG  = (float*)(smp + SM_SG);            // [64][33]
    float* red = (float*)(smp + SM_RED);           // [256][8]

    // per-lane ldmatrix offsets within a buffer
    const int ti = lane >> 3;
    const uint32_t aoff = (uint32_t)((wm * 16 + (lane & 7) + (ti & 1) * 8) * 144 + ((ti >> 1) * 8) * 2);
    const uint32_t boff = (uint32_t)((wn * 16 + (lane & 7) + (ti >> 1) * 8) * 144 + ((ti & 1) * 8) * 2);
    // epilogue fragment positions
    const int r_in = lane >> 2;            // 0..7
    const int cq   = lane & 3;

    unsigned int epoch = 0;

    // ---- Phase 0: split conversions ----
    for (size_t i = gtid; i < (size_t)TT * BB * CC; i += GSTRIDE)
        split2(x[i], d_xhi[i], d_xlo[i]);
    for (size_t i = gtid; i < (size_t)LL * 2048 * 512; i += GSTRIDE) {
        const size_t l2 = i / (2048 * 512), r = i % (2048 * 512);
        const size_t n = r / 512, k = r % 512;
        const size_t src = l2 * 2048 * 1024 + n * 1024 + k;
        split2(Wg[src],       d_Wxhi[i], d_Wxlo[i]);
        split2(Wg[src + 512], d_Whhi[i], d_Whlo[i]);
    }
    for (size_t i = gtid; i < (size_t)LL * 2048 * 1024; i += GSTRIDE)
        split2(Wi[i], d_Wihi[i], d_Wilo[i]);

    for (int l = 0; l < LL; ++l) {
        // ---- init recurrent state ----
        {
            const float* p = h0 + (size_t)l * 4 * BHN;
            for (int i = gtid; i < BHN; i += GSTRIDE) {
                split2(p[i], d_hhi[i], d_hlo[i]);
                d_c[i] = p[BHN + i];
                split2(p[2 * BHN + i], d_hihi[0][i], d_hilo[0][i]);
                d_ci[i] = p[3 * BHN + i];
            }
        }
        const bf16* Axh = ((l == 0) ? d_xhi : d_y0hi) + m0 * 512;
        const bf16* Axl = ((l == 0) ? d_xlo : d_y0lo) + m0 * 512;
        const bf16* Bxh = d_Wxhi + (size_t)l * 2048 * 512;
        const bf16* Bxl = d_Wxlo + (size_t)l * 2048 * 512;
        const bf16* Bhh = d_Whhi + (size_t)l * 2048 * 512;
        const bf16* Bhl = d_Whlo + (size_t)l * 2048 * 512;
        const bf16* Bih = d_Wihi + (size_t)l * 2048 * 1024;
        const bf16* Bil_ = d_Wilo + (size_t)l * 2048 * 1024;
        const float* bgl = bg + (size_t)l * 2048;
        const float* bil = bi + (size_t)l * 2048;

        gsync(epoch);   // conversions + state init visible; prev layer's y0 planes complete

        // ---- Phase A (parallel over t, t-split across groups): Z[t] = x_t @ Wx^T + bg ----
        for (int t = kg; t < TT; t += 2) {
            float acc[3][2][4];
            run_gemm(gp, gp_u,
                     Axh + (size_t)t * BB * 512, Axl + (size_t)t * BB * 512,
                     Axh, Axl, Bxh, Bxl, 64, 0, 1, 8, 8, j0, t128, barid, aoff, boff, acc);
            float* Zt = d_Z + ((size_t)t * NCTA + cta) * 2048;
            #pragma unroll
            for (int t2 = 0; t2 < 2; ++t2) {
                const int c0  = wn * 16 + t2 * 8 + cq * 2;
                const int wr0 = ((c0 >> 3) << 9) + j0 + (c0 & 7);
                const float b0v = bgl[wr0], b1v = bgl[wr0 + 1];
                const int r0 = wm * 16 + r_in;
                Zt[(r0    ) * 32 + c0    ] = acc[0][t2][0] + acc[1][t2][0] + acc[2][t2][0] + b0v;
                Zt[(r0    ) * 32 + c0 + 1] = acc[0][t2][1] + acc[1][t2][1] + acc[2][t2][1] + b1v;
                Zt[(r0 + 8) * 32 + c0    ] = acc[0][t2][2] + acc[1][t2][2] + acc[2][t2][2] + b0v;
                Zt[(r0 + 8) * 32 + c0 + 1] = acc[0][t2][3] + acc[1][t2][3] + acc[2][t2][3] + b1v;
            }
        }
        gsync(epoch);

        // ---- Sequential recurrence (k-split across groups + smem reduction) ----
        for (int t = 0; t < TT; ++t) {
            const int par = t & 1;

            // outer: gates = h @ Wh^T + Z[t]   (bias already folded into Z)
            {
                float acc[3][2][4];
                run_gemm(gp, gp_u,
                         d_hhi + m0 * 512, d_hlo + m0 * 512,
                         d_hhi, d_hlo, Bhh, Bhl, 64, kg, 2, 8, 8,
                         j0, t128, barid, aoff, boff, acc);
                if (kg == 1) {
                    #pragma unroll
                    for (int t2 = 0; t2 < 2; ++t2)
                        #pragma unroll
                        for (int i = 0; i < 4; ++i)
                            red[t128 * 8 + t2 * 4 + i] =
                                acc[0][t2][i] + acc[1][t2][i] + acc[2][t2][i];
                }
                __syncthreads();
                if (kg == 0) {
                    const float* Zt = d_Z + ((size_t)t * NCTA + cta) * 2048;
                    #pragma unroll
                    for (int t2 = 0; t2 < 2; ++t2) {
                        const int c0 = wn * 16 + t2 * 8 + cq * 2;
                        const int r0 = wm * 16 + r_in;
                        const float s0 = acc[0][t2][0] + acc[1][t2][0] + acc[2][t2][0] + red[t128 * 8 + t2 * 4 + 0];
                        const float s1 = acc[0][t2][1] + acc[1][t2][1] + acc[2][t2][1] + red[t128 * 8 + t2 * 4 + 1];
                        const float s2 = acc[0][t2][2] + acc[1][t2][2] + acc[2][t2][2] + red[t128 * 8 + t2 * 4 + 2];
                        const float s3 = acc[0][t2][3] + acc[1][t2][3] + acc[2][t2][3] + red[t128 * 8 + t2 * 4 + 3];
                        sG[(r0    ) * 33 + c0    ] = s0 + Zt[(r0    ) * 32 + c0    ];
                        sG[(r0    ) * 33 + c0 + 1] = s1 + Zt[(r0    ) * 32 + c0 + 1];
                        sG[(r0 + 8) * 33 + c0    ] = s2 + Zt[(r0 + 8) * 32 + c0    ];
                        sG[(r0 + 8) * 33 + c0 + 1] = s3 + Zt[(r0 + 8) * 32 + c0 + 1];
                    }
                }
                __syncthreads();
                {   // 512 threads, one gate element each
                    const int jj  = tid & 7;
                    const int row = tid >> 3;
                    const int idx = (m0 + row) * HH + j0 + jj;
                    const float gi = sG[row * 33 + jj];
                    const float gf = sG[row * 33 +  8 + jj];
                    const float go = sG[row * 33 + 16 + jj];
                    const float gc = sG[row * 33 + 24 + jj];
                    const float cellv = sigmf(gf) * d_c[idx] + sigmf(gi) * tanhf(gc);
                    split2(cellv, d_cellhi[idx], d_celllo[idx]);
                    d_sigo[idx] = sigmf(go);
                }
            }
            gsync(epoch);   // cell planes + sigo complete before inner GEMM

            // inner: gates2 = [cell, hi] @ Wi^T + bi
            {
                float acc[3][2][4];
                run_gemm(gp, gp_u,
                         d_cellhi + m0 * 512, d_celllo + m0 * 512,
                         d_hihi[par] + m0 * 512, d_hilo[par] + m0 * 512,
                         Bih, Bil_, 128, kg, 2, 16, 8,
                         j0, t128, barid, aoff, boff, acc);
                if (kg == 1) {
                    #pragma unroll
                    for (int t2 = 0; t2 < 2; ++t2)
                        #pragma unroll
                        for (int i = 0; i < 4; ++i)
                            red[t128 * 8 + t2 * 4 + i] =
                                acc[0][t2][i] + acc[1][t2][i] + acc[2][t2][i];
                }
                __syncthreads();
                if (kg == 0) {
                    #pragma unroll
                    for (int t2 = 0; t2 < 2; ++t2) {
                        const int c0  = wn * 16 + t2 * 8 + cq * 2;
                        const int wr0 = ((c0 >> 3) << 9) + j0 + (c0 & 7);
                        const float b0v = bil[wr0], b1v = bil[wr0 + 1];
                        const int r0 = wm * 16 + r_in;
                        sG[(r0    ) * 33 + c0    ] = acc[0][t2][0] + acc[1][t2][0] + acc[2][t2][0] + red[t128 * 8 + t2 * 4 + 0] + b0v;
                        sG[(r0    ) * 33 + c0 + 1] = acc[0][t2][1] + acc[1][t2][1] + acc[2][t2][1] + red[t128 * 8 + t2 * 4 + 1] + b1v;
                        sG[(r0 + 8) * 33 + c0    ] = acc[0][t2][2] + acc[1][t2][2] + acc[2][t2][2] + red[t128 * 8 + t2 * 4 + 2] + b0v;
                        sG[(r0 + 8) * 33 + c0 + 1] = acc[0][t2][3] + acc[1][t2][3] + acc[2][t2][3] + red[t128 * 8 + t2 * 4 + 3] + b1v;
                    }
                }
                __syncthreads();
                {   // 512 threads, one element each
                    const int jj  = tid & 7;
                    const int row = tid >> 3;
                    const int idx = (m0 + row) * HH + j0 + jj;
                    const float gi = sG[row * 33 + jj];
                    const float gf = sG[row * 33 +  8 + jj];
                    const float go = sG[row * 33 + 16 + jj];
                    const float gc = sG[row * 33 + 24 + jj];
                    const float cin = sigmf(gf) * d_ci[idx] + sigmf(gi) * tanhf(gc);
                    const float hin = sigmf(go) * tanhf(cin);
                    const float hn  = d_sigo[idx] * tanhf(hin);
                    d_ci[idx] = cin;
                    d_c[idx]  = hin;                           // carry: c <- hi_n
                    split2(hin, d_hihi[par ^ 1][idx], d_hilo[par ^ 1][idx]);
                    split2(hn,  d_hhi[idx], d_hlo[idx]);
                    if (l == 0) {
                        split2(hn, d_y0hi[(size_t)t * BHN + idx], d_y0lo[(size_t)t * BHN + idx]);
                    } else {
                        out[(size_t)t * BHN + idx] = hn;
                    }
                }
            }
            gsync(epoch);   // h/hi/c/ci planes complete before next step
        }
    }
}

extern "C" void kernel_launch(void* const* d_in, const int* in_sizes, int n_in,
                              void* d_out, int out_size)
{
    const float* x  = (const float*)d_in[0];   // (T,B,C)
    const float* h0 = (const float*)d_in[1];   // (L,4,B,H)
    const float* Wg = (const float*)d_in[2];   // (L,4H,C+H)
    const float* bg = (const float*)d_in[3];   // (L,4H)
    const float* Wi = (const float*)d_in[4];   // (L,4H,2H)
    const float* bi = (const float*)d_in[5];   // (L,4H)
    float* out = (float*)d_out;                // (T,B,H) f32

    cudaFuncSetAttribute(nested_lstm_persistent,
                         cudaFuncAttributeMaxDynamicSharedMemorySize, SMEM_DYN);
    reset_bar_kernel<<<1, 1>>>();
    nested_lstm_persistent<<<NCTA, NTH, SMEM_DYN>>>(x, h0, Wg, bg, Wi, bi, out);
}

// round 16
// speedup vs baseline: 2.4814x; 1.0002x over previous
#include <cuda_runtime.h>
#include <cuda_bf16.h>
#include <math.h>
#include <stdint.h>

// Problem constants (fixed by the reference)
#define TT 256
#define BB 128
#define CC 512
#define HH 512
#define LL 2
#define BHN (BB*HH)          // 65536
#define NCTA 128             // persistent grid, all co-resident
#define NTH 512              // 2 k-groups x 8 warps

// per-buffer layout (bytes). Row pitch 144B = 72 halves -> conflict-free ldmatrix.
#define OFF_AHI 0
#define OFF_ALO 9216                 // 64 rows * 144
#define OFF_BHI 18432
#define OFF_BLO 23040                // +32*144
#define BUFSZ   27648
// smem map: [group0 buf0][group0 buf1][group1 buf0][group1 buf1][sG][red]
#define SM_SG   (4*BUFSZ)            // 110592
#define SM_RED  (SM_SG + 8448)       // sG = 64*33*4
#define SMEM_DYN (SM_RED + 8192 + 1024)

typedef __nv_bfloat16 bf16;

// ---------------- scratch (static __device__, no allocations) ----------------
__device__ bf16 d_xhi [(size_t)TT*BB*CC];     // split input x
__device__ bf16 d_xlo [(size_t)TT*BB*CC];
__device__ bf16 d_y0hi[(size_t)TT*BB*HH];     // split layer-0 output
__device__ bf16 d_y0lo[(size_t)TT*BB*HH];
__device__ bf16 d_Wxhi[(size_t)LL*2048*512];  // Wg x-columns  [l][n][k]
__device__ bf16 d_Wxlo[(size_t)LL*2048*512];
__device__ bf16 d_Whhi[(size_t)LL*2048*512];  // Wg h-columns  [l][n][k]
__device__ bf16 d_Whlo[(size_t)LL*2048*512];
__device__ bf16 d_Wihi[(size_t)LL*2048*1024]; // Wi            [l][n][k]
__device__ bf16 d_Wilo[(size_t)LL*2048*1024];
__device__ float d_Z[(size_t)TT*NCTA*2048];   // x-part of outer gates (+bg), [t][cta][64][32]
__device__ bf16 d_hhi[BHN],    d_hlo[BHN];    // outer hidden planes
__device__ bf16 d_cellhi[BHN], d_celllo[BHN]; // outer candidate cell planes
__device__ bf16 d_hihi[2][BHN], d_hilo[2][BHN]; // inner hidden ping-pong planes
__device__ float d_c[BHN];                    // outer cell state (fp32)
__device__ float d_ci[BHN];                   // inner cell state (fp32)
__device__ float d_sigo[BHN];                 // sigmoid(outer o-gate)
__device__ unsigned int g_bar;

__device__ __forceinline__ float sigmf(float x) { return 1.0f / (1.0f + expf(-x)); }

__device__ __forceinline__ void split2(float v, bf16& h, bf16& l)
{
    h = __float2bfloat16(v);
    l = __float2bfloat16(v - __bfloat162float(h));
}

__global__ void reset_bar_kernel() { g_bar = 0u; }

__device__ __forceinline__ void gsync(unsigned int& epoch)
{
    ++epoch;
    __syncthreads();
    if (threadIdx.x == 0) {
        __threadfence();
        atomicAdd(&g_bar, 1u);
        const unsigned int target = epoch * (unsigned int)NCTA;
        while (*(volatile unsigned int*)&g_bar < target) { }
        __threadfence();
    }
    __syncthreads();
}

__device__ __forceinline__ uint32_t smem_u32(const void* p)
{
    uint32_t a;
    asm("{ .reg .u64 t; cvta.to.shared.u64 t, %1; cvt.u32.u64 %0, t; }" : "=r"(a) : "l"(p));
    return a;
}

#define GBAR(id) asm volatile("bar.sync %0, 256;" :: "r"(id) : "memory")

#define LDSM4(r, addr) \
    asm volatile("ldmatrix.sync.aligned.m8n8.x4.shared.b16 {%0,%1,%2,%3}, [%4];" \
        : "=r"((r)[0]), "=r"((r)[1]), "=r"((r)[2]), "=r"((r)[3]) : "r"(addr))

#define MMA16816(d, a, b0, b1) \
    asm volatile("mma.sync.aligned.m16n8k16.row.col.f32.bf16.bf16.f32 " \
        "{%0,%1,%2,%3}, {%4,%5,%6,%7}, {%8,%9}, {%0,%1,%2,%3};" \
        : "+f"((d)[0]), "+f"((d)[1]), "+f"((d)[2]), "+f"((d)[3]) \
        : "r"((a)[0]), "r"((a)[1]), "r"((a)[2]), "r"((a)[3]), "r"(b0), "r"(b1))

// ---------------- staging loads (global -> regs), 256-thread group ----------------
// A tile: 64 rows x 64 k-halves per plane. Row stride 512 halves = 64 uint4.
__device__ __forceinline__ void lda(const bf16* Ah, const bf16* Al, int c_eff, int t128,
                                    uint4* pah, uint4* pal)
{
    const uint4* gh = (const uint4*)Ah;
    const uint4* gl = (const uint4*)Al;
    #pragma unroll
    for (int i = 0; i < 2; ++i) {
        const int u = t128 + i * 256;
        const int row = u >> 3, q = u & 7;
        const int gi = row * 64 + c_eff * 8 + q;
        pah[i] = gh[gi];
        pal[i] = gl[gi];
    }
}

// B tile: 32 cols x 64 k-halves per plane. col c -> weight row ((c>>3)<<9)+j0+(c&7).
__device__ __forceinline__ void ldb(const bf16* Bh, const bf16* Bl, int c, int strideB4,
                                    int j0, int t128, uint4& pbh, uint4& pbl)
{
    const int col = t128 >> 3, q = t128 & 7;
    const int wr = ((col >> 3) << 9) + j0 + (col & 7);
    const int gi = wr * strideB4 + c * 8 + q;
    pbh = ((const uint4*)Bh)[gi];
    pbl = ((const uint4*)Bl)[gi];
}

// ---------------- split-bf16 HMMA GEMM over chunks c = cstart, cstart+cstride, ... < nct ----
// D[64x32] partial = A[64 x (chunks)] @ W[32 x (chunks)]^T, per 256-thread group.
// acc[3][2][4]: term (hh,lh,hl) x n8-tile x frag. A source switches at global chunk sc.
__device__ void run_gemm(unsigned char* gp, uint32_t gp_u,
                         const bf16* A0h, const bf16* A0l,
                         const bf16* A1h, const bf16* A1l,
                         const bf16* Bh,  const bf16* Bl,
                         int strideB4, int cstart, int cstride, int nct, int sc,
                         int j0, int t128, int barid,
                         uint32_t aoff, uint32_t boff,
                         float acc[3][2][4])
{
    #pragma unroll
    for (int s = 0; s < 3; ++s)
        #pragma unroll
        for (int t = 0; t < 2; ++t)
            #pragma unroll
            for (int i = 0; i < 4; ++i) acc[s][t][i] = 0.0f;

    uint4 pah[2], pal[2], pbh, pbl;
    lda(A0h, A0l, cstart, t128, pah, pal);            // cstart < sc always here
    ldb(Bh, Bl, cstart, strideB4, j0, t128, pbh, pbl);

    int ci = 0;
    #pragma unroll 1
    for (int c = cstart; c < nct; c += cstride, ++ci) {
        unsigned char* buf = gp + (ci & 1) * BUFSZ;
        #pragma unroll
        for (int i = 0; i < 2; ++i) {
            const int u = t128 + i * 256;
            const int row = u >> 3, q = u & 7;
            *(uint4*)(buf + OFF_AHI + row * 144 + q * 16) = pah[i];
            *(uint4*)(buf + OFF_ALO + row * 144 + q * 16) = pal[i];
        }
        {
            const int col = t128 >> 3, q = t128 & 7;
            *(uint4*)(buf + OFF_BHI + col * 144 + q * 16) = pbh;
            *(uint4*)(buf + OFF_BLO + col * 144 + q * 16) = pbl;
        }
        // prefetch next chunk while this one is consumed
        const int cn = c + cstride;
        if (cn < nct) {
            if (cn < sc) lda(A0h, A0l, cn, t128, pah, pal);
            else         lda(A1h, A1l, cn - sc, t128, pah, pal);
            ldb(Bh, Bl, cn, strideB4, j0, t128, pbh, pbl);
        }
        GBAR(barid);

        const uint32_t bu = gp_u + (ci & 1) * BUFSZ;
        #pragma unroll
        for (int k16 = 0; k16 < 4; ++k16) {
            uint32_t ah[4], al[4], bh[4], bl[4];
            LDSM4(ah, bu + OFF_AHI + aoff + k16 * 32);
            LDSM4(al, bu + OFF_ALO + aoff + k16 * 32);
            LDSM4(bh, bu + OFF_BHI + boff + k16 * 32);
            LDSM4(bl, bu + OFF_BLO + boff + k16 * 32);
            MMA16816(acc[0][0], ah, bh[0], bh[1]);
            MMA16816(acc[0][1], ah, bh[2], bh[3]);
            MMA16816(acc[1][0], al, bh[0], bh[1]);
            MMA16816(acc[1][1], al, bh[2], bh[3]);
            MMA16816(acc[2][0], ah, bl[0], bl[1]);
            MMA16816(acc[2][1], ah, bl[2], bl[3]);
        }
    }
}

// ---------------- persistent kernel ----------------
__global__ __launch_bounds__(NTH, 1)
void nested_lstm_persistent(const float* __restrict__ x,
                            const float* __restrict__ h0,
                            const float* __restrict__ Wg,
                            const float* __restrict__ bg,
                            const float* __restrict__ Wi,
                            const float* __restrict__ bi,
                            float* __restrict__ out)
{
    extern __shared__ __align__(16) unsigned char dsm[];

    const int tid  = threadIdx.x;
    const int cta  = blockIdx.x;           // 0..127
    const int m0   = (cta & 1) * 64;
    const int j0   = (cta >> 1) * 8;
    const int kg   = tid >> 8;             // k-group 0/1
    const int t128 = tid & 255;
    const int lane = tid & 31;
    const int w    = t128 >> 5;            // warp-in-group 0..7
    const int wm   = w >> 1;               // row group: rows m0 + wm*16 .. +15
    const int wn   = w & 1;                // col group: cols wn*16 .. +15
    const int barid = kg + 1;
    const int gtid = cta * NTH + tid;
    const int GSTRIDE = NCTA * NTH;

    const uint32_t raw_u = smem_u32(dsm);
    const uint32_t smp_u = (raw_u + 1023u) & ~1023u;
    unsigned char* smp = dsm + (smp_u - raw_u);
    unsigned char* gp  = smp + kg * 2 * BUFSZ;     // this group's buffer pair
    const uint32_t gp_u = smp_u + kg * 2 * BUFSZ;
    float* sG  = (float*)(smp + SM_SG);            // [64][33]
    float* red = (float*)(smp + SM_RED);           // [256][8]

    // per-lane ldmatrix offsets within a buffer
    const int ti = lane >> 3;
    const uint32_t aoff = (uint32_t)((wm * 16 + (lane & 7) + (ti & 1) * 8) * 144 + ((ti >> 1) * 8) * 2);
    const uint32_t boff = (uint32_t)((wn * 16 + (lane & 7) + (ti >> 1) * 8) * 144 + ((ti & 1) * 8) * 2);
    // epilogue fragment positions
    const int r_in = lane >> 2;            // 0..7
    const int cq   = lane & 3;

    unsigned int epoch = 0;

    // ---- Phase 0: split conversions ----
    for (size_t i = gtid; i < (size_t)TT * BB * CC; i += GSTRIDE)
        split2(x[i], d_xhi[i], d_xlo[i]);
    for (size_t i = gtid; i < (size_t)LL * 2048 * 512; i += GSTRIDE) {
        const size_t l2 = i / (2048 * 512), r = i % (2048 * 512);
        const size_t n = r / 512, k = r % 512;
        const size_t src = l2 * 2048 * 1024 + n * 1024 + k;
        split2(Wg[src],       d_Wxhi[i], d_Wxlo[i]);
        split2(Wg[src + 512], d_Whhi[i], d_Whlo[i]);
    }
    for (size_t i = gtid; i < (size_t)LL * 2048 * 1024; i += GSTRIDE)
        split2(Wi[i], d_Wihi[i], d_Wilo[i]);

    for (int l = 0; l < LL; ++l) {
        // ---- init recurrent state ----
        {
            const float* p = h0 + (size_t)l * 4 * BHN;
            for (int i = gtid; i < BHN; i += GSTRIDE) {
                split2(p[i], d_hhi[i], d_hlo[i]);
                d_c[i] = p[BHN + i];
                split2(p[2 * BHN + i], d_hihi[0][i], d_hilo[0][i]);
                d_ci[i] = p[3 * BHN + i];
            }
        }
        const bf16* Axh = ((l == 0) ? d_xhi : d_y0hi) + m0 * 512;
        const bf16* Axl = ((l == 0) ? d_xlo : d_y0lo) + m0 * 512;
        const bf16* Bxh = d_Wxhi + (size_t)l * 2048 * 512;
        const bf16* Bxl = d_Wxlo + (size_t)l * 2048 * 512;
        const bf16* Bhh = d_Whhi + (size_t)l * 2048 * 512;
        const bf16* Bhl = d_Whlo + (size_t)l * 2048 * 512;
        const bf16* Bih = d_Wihi + (size_t)l * 2048 * 1024;
        const bf16* Bil_ = d_Wilo + (size_t)l * 2048 * 1024;
        const float* bgl = bg + (size_t)l * 2048;
        const float* bil = bi + (size_t)l * 2048;

        gsync(epoch);   // conversions + state init visible; prev layer's y0 planes complete

        // ---- Phase A (parallel over t, t-split across groups): Z[t] = x_t @ Wx^T + bg ----
        for (int t = kg; t < TT; t += 2) {
            float acc[3][2][4];
            run_gemm(gp, gp_u,
                     Axh + (size_t)t * BB * 512, Axl + (size_t)t * BB * 512,
                     Axh, Axl, Bxh, Bxl, 64, 0, 1, 8, 8, j0, t128, barid, aoff, boff, acc);
            float* Zt = d_Z + ((size_t)t * NCTA + cta) * 2048;
            #pragma unroll
            for (int t2 = 0; t2 < 2; ++t2) {
                const int c0  = wn * 16 + t2 * 8 + cq * 2;
                const int wr0 = ((c0 >> 3) << 9) + j0 + (c0 & 7);
                const float b0v = bgl[wr0], b1v = bgl[wr0 + 1];
                const int r0 = wm * 16 + r_in;
                Zt[(r0    ) * 32 + c0    ] = acc[0][t2][0] + acc[1][t2][0] + acc[2][t2][0] + b0v;
                Zt[(r0    ) * 32 + c0 + 1] = acc[0][t2][1] + acc[1][t2][1] + acc[2][t2][1] + b1v;
                Zt[(r0 + 8) * 32 + c0    ] = acc[0][t2][2] + acc[1][t2][2] + acc[2][t2][2] + b0v;
                Zt[(r0 + 8) * 32 + c0 + 1] = acc[0][t2][3] + acc[1][t2][3] + acc[2][t2][3] + b1v;
            }
        }
        gsync(epoch);

        // ---- Sequential recurrence (k-split across groups + smem reduction) ----
        for (int t = 0; t < TT; ++t) {
            const int par = t & 1;

            // outer: gates = h @ Wh^T + Z[t]   (bias already folded into Z)
            {
                float acc[3][2][4];
                run_gemm(gp, gp_u,
                         d_hhi + m0 * 512, d_hlo + m0 * 512,
                         d_hhi, d_hlo, Bhh, Bhl, 64, kg, 2, 8, 8,
                         j0, t128, barid, aoff, boff, acc);
                if (kg == 1) {
                    #pragma unroll
                    for (int t2 = 0; t2 < 2; ++t2)
                        #pragma unroll
                        for (int i = 0; i < 4; ++i)
                            red[t128 * 8 + t2 * 4 + i] =
                                acc[0][t2][i] + acc[1][t2][i] + acc[2][t2][i];
                }
                __syncthreads();
                if (kg == 0) {
                    const float* Zt = d_Z + ((size_t)t * NCTA + cta) * 2048;
                    #pragma unroll
                    for (int t2 = 0; t2 < 2; ++t2) {
                        const int c0 = wn * 16 + t2 * 8 + cq * 2;
                        const int r0 = wm * 16 + r_in;
                        const float s0 = acc[0][t2][0] + acc[1][t2][0] + acc[2][t2][0] + red[t128 * 8 + t2 * 4 + 0];
                        const float s1 = acc[0][t2][1] + acc[1][t2][1] + acc[2][t2][1] + red[t128 * 8 + t2 * 4 + 1];
                        const float s2 = acc[0][t2][2] + acc[1][t2][2] + acc[2][t2][2] + red[t128 * 8 + t2 * 4 + 2];
                        const float s3 = acc[0][t2][3] + acc[1][t2][3] + acc[2][t2][3] + red[t128 * 8 + t2 * 4 + 3];
                        sG[(r0    ) * 33 + c0    ] = s0 + Zt[(r0    ) * 32 + c0    ];
                        sG[(r0    ) * 33 + c0 + 1] = s1 + Zt[(r0    ) * 32 + c0 + 1];
                        sG[(r0 + 8) * 33 + c0    ] = s2 + Zt[(r0 + 8) * 32 + c0    ];
                        sG[(r0 + 8) * 33 + c0 + 1] = s3 + Zt[(r0 + 8) * 32 + c0 + 1];
                    }
                }
                __syncthreads();
                {   // 512 threads, one gate element each
                    const int jj  = tid & 7;
                    const int row = tid >> 3;
                    const int idx = (m0 + row) * HH + j0 + jj;
                    const float gi = sG[row * 33 + jj];
                    const float gf = sG[row * 33 +  8 + jj];
                    const float go = sG[row * 33 + 16 + jj];
                    const float gc = sG[row * 33 + 24 + jj];
                    const float cellv = sigmf(gf) * d_c[idx] + sigmf(gi) * tanhf(gc);
                    split2(cellv, d_cellhi[idx], d_celllo[idx]);
                    d_sigo[idx] = sigmf(go);
                }
            }
            gsync(epoch);   // cell planes + sigo complete before inner GEMM

            // inner: gates2 = [cell, hi] @ Wi^T + bi
            {
                float acc[3][2][4];
                run_gemm(gp, gp_u,
                         d_cellhi + m0 * 512, d_celllo + m0 * 512,
                         d_hihi[par] + m0 * 512, d_hilo[par] + m0 * 512,
                         Bih, Bil_, 128, kg, 2, 16, 8,
                         j0, t128, barid, aoff, boff, acc);
                if (kg == 1) {
                    #pragma unroll
                    for (int t2 = 0; t2 < 2; ++t2)
                        #pragma unroll
                        for (int i = 0; i < 4; ++i)
                            red[t128 * 8 + t2 * 4 + i] =
                                acc[0][t2][i] + acc[1][t2][i] + acc[2][t2][i];
                }
                __syncthreads();
                if (kg == 0) {
                    #pragma unroll
                    for (int t2 = 0; t2 < 2; ++t2) {
                        const int c0  = wn * 16 + t2 * 8 + cq * 2;
                        const int wr0 = ((c0 >> 3) << 9) + j0 + (c0 & 7);
                        const float b0v = bil[wr0], b1v = bil[wr0 + 1];
                        const int r0 = wm * 16 + r_in;
                        sG[(r0    ) * 33 + c0    ] = acc[0][t2][0] + acc[1][t2][0] + acc[2][t2][0] + red[t128 * 8 + t2 * 4 + 0] + b0v;
                        sG[(r0    ) * 33 + c0 + 1] = acc[0][t2][1] + acc[1][t2][1] + acc[2][t2][1] + red[t128 * 8 + t2 * 4 + 1] + b1v;
                        sG[(r0 + 8) * 33 + c0    ] = acc[0][t2][2] + acc[1][t2][2] + acc[2][t2][2] + red[t128 * 8 + t2 * 4 + 2] + b0v;
                        sG[(r0 + 8) * 33 + c0 + 1] = acc[0][t2][3] + acc[1][t2][3] + acc[2][t2][3] + red[t128 * 8 + t2 * 4 + 3] + b1v;
                    }
                }
                __syncthreads();
                {   // 512 threads, one element each
                    const int jj  = tid & 7;
                    const int row = tid >> 3;
                    const int idx = (m0 + row) * HH + j0 + jj;
                    const float gi = sG[row * 33 + jj];
                    const float gf = sG[row * 33 +  8 + jj];
                    const float go = sG[row * 33 + 16 + jj];
                    const float gc = sG[row * 33 + 24 + jj];
                    const float cin = sigmf(gf) * d_ci[idx] + sigmf(gi) * tanhf(gc);
                    const float hin = sigmf(go) * tanhf(cin);
                    const float hn  = d_sigo[idx] * tanhf(hin);
                    d_ci[idx] = cin;
                    d_c[idx]  = hin;                           // carry: c <- hi_n
                    split2(hin, d_hihi[par ^ 1][idx], d_hilo[par ^ 1][idx]);
                    split2(hn,  d_hhi[idx], d_hlo[idx]);
                    if (l == 0) {
                        split2(hn, d_y0hi[(size_t)t * BHN + idx], d_y0lo[(size_t)t * BHN + idx]);
                    } else {
                        out[(size_t)t * BHN + idx] = hn;
                    }
                }
            }
            gsync(epoch);   // h/hi/c/ci planes complete before next step
        }
    }
}

extern "C" void kernel_launch(void* const* d_in, const int* in_sizes, int n_in,
                              void* d_out, int out_size)
{
    const float* x  = (const float*)d_in[0];   // (T,B,C)
    const float* h0 = (const float*)d_in[1];   // (L,4,B,H)
    const float* Wg = (const float*)d_in[2];   // (L,4H,C+H)
    const float* bg = (const float*)d_in[3];   // (L,4H)
    const float* Wi = (const float*)d_in[4];   // (L,4H,2H)
    const float* bi = (const float*)d_in[5];   // (L,4H)
    float* out = (float*)d_out;                // (T,B,H) f32

    cudaFuncSetAttribute(nested_lstm_persistent,
                         cudaFuncAttributeMaxDynamicSharedMemorySize, SMEM_DYN);
    reset_bar_kernel<<<1, 1>>>();
    nested_lstm_persistent<<<NCTA, NTH, SMEM_DYN>>>(x, h0, Wg, bg, Wi, bi, out);
}

// round 17
// speedup vs baseline: 2.5487x; 1.0271x over previous
#include <cuda_runtime.h>
#include <cuda_bf16.h>
#include <math.h>
#include <stdint.h>

// Problem constants (fixed by the reference)
#define TT 256
#define BB 128
#define CC 512
#define HH 512
#define LL 2
#define BHN (BB*HH)          // 65536
#define NCTA 128             // persistent grid, all co-resident
#define NTH 512              // 2 k-groups x 8 warps

// K=128 chunk staging. Row pitch 272B (256B row + 16B skew) -> conflict-free ldmatrix.
#define PITCH   272
#define OFF_AHI 0
#define OFF_ALO 17408                // 64 rows * 272
#define OFF_BHI 34816
#define OFF_BLO 43520                // +32*272
#define BUFSZ   52224
// smem map: [g0 buf0][g0 buf1][g1 buf0][g1 buf1][sG][red]
#define SM_SG   (4*BUFSZ)            // 208896
#define SM_RED  (SM_SG + 8448)       // sG = 64*33*4
#define SMEM_DYN (SM_RED + 8192)     // 225536 (< 227KB cap)

typedef __nv_bfloat16 bf16;

// ---------------- scratch (static __device__, no allocations) ----------------
__device__ bf16 d_xhi [(size_t)TT*BB*CC];     // split input x
__device__ bf16 d_xlo [(size_t)TT*BB*CC];
__device__ bf16 d_y0hi[(size_t)TT*BB*HH];     // split layer-0 output
__device__ bf16 d_y0lo[(size_t)TT*BB*HH];
__device__ bf16 d_Wxhi[(size_t)LL*2048*512];  // Wg x-columns  [l][n][k]
__device__ bf16 d_Wxlo[(size_t)LL*2048*512];
__device__ bf16 d_Whhi[(size_t)LL*2048*512];  // Wg h-columns  [l][n][k]
__device__ bf16 d_Whlo[(size_t)LL*2048*512];
__device__ bf16 d_Wihi[(size_t)LL*2048*1024]; // Wi            [l][n][k]
__device__ bf16 d_Wilo[(size_t)LL*2048*1024];
__device__ float d_Z[(size_t)TT*NCTA*2048];   // x-part of outer gates (+bg), [t][cta][64][32]
__device__ bf16 d_hhi[BHN],    d_hlo[BHN];    // outer hidden planes
__device__ bf16 d_cellhi[BHN], d_celllo[BHN]; // outer candidate cell planes
__device__ bf16 d_hihi[2][BHN], d_hilo[2][BHN]; // inner hidden ping-pong planes
__device__ unsigned int g_seg[8];             // two-level grid barrier: segment counters
__device__ unsigned int g_root;               // root counter

// fast gates: __expf/__fdividef, rel err ~1e-6 (<< bf16-split noise 1e-5)
__device__ __forceinline__ float fsig(float x)
{
    return __fdividef(1.0f, 1.0f + __expf(-x));
}
__device__ __forceinline__ float ftanh(float x)
{
    x = fminf(fmaxf(x, -15.0f), 15.0f);       // avoid exp overflow; tanh(15)==1 in fp32
    const float e = __expf(2.0f * x);
    return __fdividef(e - 1.0f, e + 1.0f);
}

__device__ __forceinline__ void split2(float v, bf16& h, bf16& l)
{
    h = __float2bfloat16(v);
    l = __float2bfloat16(v - __bfloat162float(h));
}

__global__ void reset_bar_kernel()
{
    for (int i = 0; i < 8; ++i) g_seg[i] = 0u;
    g_root = 0u;
}

// Two-level grid barrier: 8 segments x 16 CTAs -> root. Monotonic epochs.
__device__ __forceinline__ void gsync(unsigned int& epoch, int cta)
{
    ++epoch;
    __syncthreads();
    if (threadIdx.x == 0) {
        __threadfence();
        const unsigned int old = atomicAdd(&g_seg[cta >> 4], 1u);
        if (old == epoch * 16u - 1u) atomicAdd(&g_root, 1u);   // last arrival in segment
        const unsigned int target = epoch * 8u;
        while (*(volatile unsigned int*)&g_root < target) { }
        __threadfence();
    }
    __syncthreads();
}

__device__ __forceinline__ uint32_t smem_u32(const void* p)
{
    uint32_t a;
    asm("{ .reg .u64 t; cvta.to.shared.u64 t, %1; cvt.u32.u64 %0, t; }" : "=r"(a) : "l"(p));
    return a;
}

#define GBAR(id) asm volatile("bar.sync %0, 256;" :: "r"(id) : "memory")

#define CPASYNC16(saddr, gptr) \
    asm volatile("cp.async.cg.shared.global [%0], [%1], 16;" :: "r"(saddr), "l"(gptr) : "memory")
#define CPCOMMIT() asm volatile("cp.async.commit_group;" ::: "memory")
#define CPWAIT1()  asm volatile("cp.async.wait_group 1;"  ::: "memory")

#define LDSM4(r, addr) \
    asm volatile("ldmatrix.sync.aligned.m8n8.x4.shared.b16 {%0,%1,%2,%3}, [%4];" \
        : "=r"((r)[0]), "=r"((r)[1]), "=r"((r)[2]), "=r"((r)[3]) : "r"(addr))

#define MMA16816(d, a, b0, b1) \
    asm volatile("mma.sync.aligned.m16n8k16.row.col.f32.bf16.bf16.f32 " \
        "{%0,%1,%2,%3}, {%4,%5,%6,%7}, {%8,%9}, {%0,%1,%2,%3};" \
        : "+f"((d)[0]), "+f"((d)[1]), "+f"((d)[2]), "+f"((d)[3]) \
        : "r"((a)[0]), "r"((a)[1]), "r"((a)[2]), "r"((a)[3]), "r"(b0), "r"(b1))

// ---------------- cp.async staging, one 256-thread group, K=128 chunk ----------------
// A tile: 64 rows x 128 halves per plane (row stride in gmem = 512 halves = 64 uint4).
__device__ __forceinline__ void stageA(uint32_t bu, const bf16* Ah, const bf16* Al,
                                       int c_eff, int t128)
{
    const uint4* gh = (const uint4*)Ah;
    const uint4* gl = (const uint4*)Al;
    #pragma unroll
    for (int i = 0; i < 4; ++i) {
        const int u = t128 + i * 256;
        const int row = u >> 4, q = u & 15;
        const int gi = row * 64 + c_eff * 16 + q;
        CPASYNC16(bu + OFF_AHI + row * PITCH + q * 16, gh + gi);
        CPASYNC16(bu + OFF_ALO + row * PITCH + q * 16, gl + gi);
    }
}

// B tile: 32 cols x 128 halves per plane. col c -> weight row ((c>>3)<<9)+j0+(c&7).
__device__ __forceinline__ void stageB(uint32_t bu, const bf16* Bh, const bf16* Bl,
                                       int c, int strideB4, int j0, int t128)
{
    #pragma unroll
    for (int i = 0; i < 2; ++i) {
        const int u = t128 + i * 256;
        const int col = u >> 4, q = u & 15;
        const int wr = ((col >> 3) << 9) + j0 + (col & 7);
        const int gi = wr * strideB4 + c * 16 + q;
        CPASYNC16(bu + OFF_BHI + col * PITCH + q * 16, (const uint4*)Bh + gi);
        CPASYNC16(bu + OFF_BLO + col * PITCH + q * 16, (const uint4*)Bl + gi);
    }
}

__device__ __forceinline__ void stage_chunk(uint32_t bu,
                                            const bf16* A0h, const bf16* A0l,
                                            const bf16* A1h, const bf16* A1l,
                                            const bf16* Bh,  const bf16* Bl,
                                            int strideB4, int c, int sc, int j0, int t128)
{
    if (c < sc) stageA(bu, A0h, A0l, c, t128);
    else        stageA(bu, A1h, A1l, c - sc, t128);
    stageB(bu, Bh, Bl, c, strideB4, j0, t128);
}

// ---------------- split-bf16 HMMA GEMM over chunks c = cstart, +cstride, ... < nct -----
// 2-stage cp.async pipeline, K=128 chunks (8 k16 steps each). Per 256-thread group.
__device__ void run_gemm(uint32_t gp_u,
                         const bf16* A0h, const bf16* A0l,
                         const bf16* A1h, const bf16* A1l,
                         const bf16* Bh,  const bf16* Bl,
                         int strideB4, int cstart, int cstride, int nct, int sc,
                         int j0, int t128, int barid,
                         uint32_t aoff, uint32_t boff,
                         float acc[3][2][4])
{
    #pragma unroll
    for (int s = 0; s < 3; ++s)
        #pragma unroll
        for (int t = 0; t < 2; ++t)
            #pragma unroll
            for (int i = 0; i < 4; ++i) acc[s][t][i] = 0.0f;

    // prologue: stage first two chunks into the two buffers
    stage_chunk(gp_u, A0h, A0l, A1h, A1l, Bh, Bl, strideB4, cstart, sc, j0, t128);
    CPCOMMIT();
    {
        const int c1 = cstart + cstride;
        if (c1 < nct)
            stage_chunk(gp_u + BUFSZ, A0h, A0l, A1h, A1l, Bh, Bl, strideB4, c1, sc, j0, t128);
        CPCOMMIT();
    }

    int ci = 0;
    #pragma unroll 1
    for (int c = cstart; c < nct; c += cstride, ++ci) {
        CPWAIT1();                 // chunk ci's copies complete
        GBAR(barid);               // visible to all warps in group
        const uint32_t bu = gp_u + (ci & 1) * BUFSZ;
        #pragma unroll
        for (int k16 = 0; k16 < 8; ++k16) {
            uint32_t ah[4], al[4], bh[4], bl[4];
            LDSM4(ah, bu + OFF_AHI + aoff + k16 * 32);
            LDSM4(al, bu + OFF_ALO + aoff + k16 * 32);
            LDSM4(bh, bu + OFF_BHI + boff + k16 * 32);
            LDSM4(bl, bu + OFF_BLO + boff + k16 * 32);
            MMA16816(acc[0][0], ah, bh[0], bh[1]);
            MMA16816(acc[0][1], ah, bh[2], bh[3]);
            MMA16816(acc[1][0], al, bh[0], bh[1]);
            MMA16816(acc[1][1], al, bh[2], bh[3]);
            MMA16816(acc[2][0], ah, bl[0], bl[1]);
            MMA16816(acc[2][1], ah, bl[2], bl[3]);
        }
        GBAR(barid);               // all warps done reading this buffer
        const int cn = c + 2 * cstride;
        if (cn < nct)
            stage_chunk(bu, A0h, A0l, A1h, A1l, Bh, Bl, strideB4, cn, sc, j0, t128);
        CPCOMMIT();                // commit every iter (empty groups keep bookkeeping exact)
    }
}

// ---------------- persistent kernel ----------------
__global__ __launch_bounds__(NTH, 1)
void nested_lstm_persistent(const float* __restrict__ x,
                            const float* __restrict__ h0,
                            const float* __restrict__ Wg,
                            const float* __restrict__ bg,
                            const float* __restrict__ Wi,
                            const float* __restrict__ bi,
                            float* __restrict__ out)
{
    extern __shared__ __align__(16) unsigned char dsm[];

    const int tid  = threadIdx.x;
    const int cta  = blockIdx.x;           // 0..127
    const int m0   = (cta & 1) * 64;
    const int j0   = (cta >> 1) * 8;
    const int kg   = tid >> 8;             // k-group 0/1
    const int t128 = tid & 255;
    const int lane = tid & 31;
    const int w    = t128 >> 5;            // warp-in-group 0..7
    const int wm   = w >> 1;               // row group: rows m0 + wm*16 .. +15
    const int wn   = w & 1;                // col group: cols wn*16 .. +15
    const int barid = kg + 1;
    const int gtid = cta * NTH + tid;
    const int GSTRIDE = NCTA * NTH;

    const uint32_t smp_u = smem_u32(dsm);
    const uint32_t gp_u  = smp_u + kg * 2 * BUFSZ;     // this group's buffer pair
    float* sG  = (float*)(dsm + SM_SG);                // [64][33]
    float* red = (float*)(dsm + SM_RED);               // [256][8]

    // per-lane ldmatrix offsets within a buffer
    const int ti = lane >> 3;
    const uint32_t aoff = (uint32_t)((wm * 16 + (lane & 7) + (ti & 1) * 8) * PITCH + ((ti >> 1) * 8) * 2);
    const uint32_t boff = (uint32_t)((wn * 16 + (lane & 7) + (ti >> 1) * 8) * PITCH + ((ti & 1) * 8) * 2);
    // epilogue fragment positions
    const int r_in = lane >> 2;            // 0..7
    const int cq   = lane & 3;

    // epilogue element owned by this thread (fixed for whole kernel)
    const int e_jj  = tid & 7;
    const int e_row = tid >> 3;
    const int e_idx = (m0 + e_row) * HH + j0 + e_jj;

    unsigned int epoch = 0;

    // ---- Phase 0: split conversions ----
    for (size_t i = gtid; i < (size_t)TT * BB * CC; i += GSTRIDE)
        split2(x[i], d_xhi[i], d_xlo[i]);
    for (size_t i = gtid; i < (size_t)LL * 2048 * 512; i += GSTRIDE) {
        const size_t l2 = i / (2048 * 512), r = i % (2048 * 512);
        const size_t n = r / 512, k = r % 512;
        const size_t src = l2 * 2048 * 1024 + n * 1024 + k;
        split2(Wg[src],       d_Wxhi[i], d_Wxlo[i]);
        split2(Wg[src + 512], d_Whhi[i], d_Whlo[i]);
    }
    for (size_t i = gtid; i < (size_t)LL * 2048 * 1024; i += GSTRIDE)
        split2(Wi[i], d_Wihi[i], d_Wilo[i]);

    for (int l = 0; l < LL; ++l) {
        // ---- init recurrent state ----
        const float* p = h0 + (size_t)l * 4 * BHN;
        for (int i = gtid; i < BHN; i += GSTRIDE) {
            split2(p[i], d_hhi[i], d_hlo[i]);
            split2(p[2 * BHN + i], d_hihi[0][i], d_hilo[0][i]);
        }
        // register-resident per-thread state (this thread's element)
        float c_r  = p[BHN + e_idx];           // outer cell state
        float ci_r = p[3 * BHN + e_idx];       // inner cell state
        float so_r = 0.0f;                     // sigmoid(outer o-gate), set each step

        const bf16* Axh = ((l == 0) ? d_xhi : d_y0hi) + m0 * 512;
        const bf16* Axl = ((l == 0) ? d_xlo : d_y0lo) + m0 * 512;
        const bf16* Bxh = d_Wxhi + (size_t)l * 2048 * 512;
        const bf16* Bxl = d_Wxlo + (size_t)l * 2048 * 512;
        const bf16* Bhh = d_Whhi + (size_t)l * 2048 * 512;
        const bf16* Bhl = d_Whlo + (size_t)l * 2048 * 512;
        const bf16* Bih = d_Wihi + (size_t)l * 2048 * 1024;
        const bf16* Bil_ = d_Wilo + (size_t)l * 2048 * 1024;
        const float* bgl = bg + (size_t)l * 2048;
        const float* bil = bi + (size_t)l * 2048;

        gsync(epoch, cta);   // conversions + plane init visible; prev layer's y0 complete

        // ---- Phase A (parallel over t, t-split across groups): Z[t] = x_t @ Wx^T + bg ----
        for (int t = kg; t < TT; t += 2) {
            float acc[3][2][4];
            run_gemm(gp_u,
                     Axh + (size_t)t * BB * 512, Axl + (size_t)t * BB * 512,
                     Axh, Axl, Bxh, Bxl, 64, 0, 1, 4, 4, j0, t128, barid, aoff, boff, acc);
            float* Zt = d_Z + ((size_t)t * NCTA + cta) * 2048;
            #pragma unroll
            for (int t2 = 0; t2 < 2; ++t2) {
                const int c0  = wn * 16 + t2 * 8 + cq * 2;
                const int wr0 = ((c0 >> 3) << 9) + j0 + (c0 & 7);
                const float b0v = bgl[wr0], b1v = bgl[wr0 + 1];
                const int r0 = wm * 16 + r_in;
                Zt[(r0    ) * 32 + c0    ] = acc[0][t2][0] + acc[1][t2][0] + acc[2][t2][0] + b0v;
                Zt[(r0    ) * 32 + c0 + 1] = acc[0][t2][1] + acc[1][t2][1] + acc[2][t2][1] + b1v;
                Zt[(r0 + 8) * 32 + c0    ] = acc[0][t2][2] + acc[1][t2][2] + acc[2][t2][2] + b0v;
                Zt[(r0 + 8) * 32 + c0 + 1] = acc[0][t2][3] + acc[1][t2][3] + acc[2][t2][3] + b1v;
            }
        }
        gsync(epoch, cta);

        // ---- Sequential recurrence (k-split across groups + smem reduction) ----
        for (int t = 0; t < TT; ++t) {
            const int par = t & 1;

            // outer: gates = h @ Wh^T + Z[t]   (bias already folded into Z)
            {
                float acc[3][2][4];
                run_gemm(gp_u,
                         d_hhi + m0 * 512, d_hlo + m0 * 512,
                         d_hhi, d_hlo, Bhh, Bhl, 64, kg, 2, 4, 4,
                         j0, t128, barid, aoff, boff, acc);
                if (kg == 1) {
                    #pragma unroll
                    for (int t2 = 0; t2 < 2; ++t2)
                        #pragma unroll
                        for (int i = 0; i < 4; ++i)
                            red[t128 * 8 + t2 * 4 + i] =
                                acc[0][t2][i] + acc[1][t2][i] + acc[2][t2][i];
                }
                __syncthreads();
                if (kg == 0) {
                    const float* Zt = d_Z + ((size_t)t * NCTA + cta) * 2048;
                    #pragma unroll
                    for (int t2 = 0; t2 < 2; ++t2) {
                        const int c0 = wn * 16 + t2 * 8 + cq * 2;
                        const int r0 = wm * 16 + r_in;
                        const float s0 = acc[0][t2][0] + acc[1][t2][0] + acc[2][t2][0] + red[t128 * 8 + t2 * 4 + 0];
                        const float s1 = acc[0][t2][1] + acc[1][t2][1] + acc[2][t2][1] + red[t128 * 8 + t2 * 4 + 1];
                        const float s2 = acc[0][t2][2] + acc[1][t2][2] + acc[2][t2][2] + red[t128 * 8 + t2 * 4 + 2];
                        const float s3 = acc[0][t2][3] + acc[1][t2][3] + acc[2][t2][3] + red[t128 * 8 + t2 * 4 + 3];
                        sG[(r0    ) * 33 + c0    ] = s0 + Zt[(r0    ) * 32 + c0    ];
                        sG[(r0    ) * 33 + c0 + 1] = s1 + Zt[(r0    ) * 32 + c0 + 1];
                        sG[(r0 + 8) * 33 + c0    ] = s2 + Zt[(r0 + 8) * 32 + c0    ];
                        sG[(r0 + 8) * 33 + c0 + 1] = s3 + Zt[(r0 + 8) * 32 + c0 + 1];
                    }
                }
                __syncthreads();
                {   // one gate element per thread; state in registers
                    const float gi = sG[e_row * 33 + e_jj];
                    const float gf = sG[e_row * 33 +  8 + e_jj];
                    const float go = sG[e_row * 33 + 16 + e_jj];
                    const float gc = sG[e_row * 33 + 24 + e_jj];
                    const float cellv = fsig(gf) * c_r + fsig(gi) * ftanh(gc);
                    split2(cellv, d_cellhi[e_idx], d_celllo[e_idx]);
                    so_r = fsig(go);
                }
            }
            gsync(epoch, cta);   // cell planes complete before inner GEMM

            // inner: gates2 = [cell, hi] @ Wi^T + bi
            {
                float acc[3][2][4];
                run_gemm(gp_u,
                         d_cellhi + m0 * 512, d_celllo + m0 * 512,
                         d_hihi[par] + m0 * 512, d_hilo[par] + m0 * 512,
                         Bih, Bil_, 128, kg, 2, 8, 4,
                         j0, t128, barid, aoff, boff, acc);
                if (kg == 1) {
                    #pragma unroll
                    for (int t2 = 0; t2 < 2; ++t2)
                        #pragma unroll
                        for (int i = 0; i < 4; ++i)
                            red[t128 * 8 + t2 * 4 + i] =
                                acc[0][t2][i] + acc[1][t2][i] + acc[2][t2][i];
                }
                __syncthreads();
                if (kg == 0) {
                    #pragma unroll
                    for (int t2 = 0; t2 < 2; ++t2) {
                        const int c0  = wn * 16 + t2 * 8 + cq * 2;
                        const int wr0 = ((c0 >> 3) << 9) + j0 + (c0 & 7);
                        const float b0v = bil[wr0], b1v = bil[wr0 + 1];
                        const int r0 = wm * 16 + r_in;
                        sG[(r0    ) * 33 + c0    ] = acc[0][t2][0] + acc[1][t2][0] + acc[2][t2][0] + red[t128 * 8 + t2 * 4 + 0] + b0v;
                        sG[(r0    ) * 33 + c0 + 1] = acc[0][t2][1] + acc[1][t2][1] + acc[2][t2][1] + red[t128 * 8 + t2 * 4 + 1] + b1v;
                        sG[(r0 + 8) * 33 + c0    ] = acc[0][t2][2] + acc[1][t2][2] + acc[2][t2][2] + red[t128 * 8 + t2 * 4 + 2] + b0v;
                        sG[(r0 + 8) * 33 + c0 + 1] = acc[0][t2][3] + acc[1][t2][3] + acc[2][t2][3] + red[t128 * 8 + t2 * 4 + 3] + b1v;
                    }
                }
                __syncthreads();
                {   // one element per thread; state in registers
                    const float gi = sG[e_row * 33 + e_jj];
                    const float gf = sG[e_row * 33 +  8 + e_jj];
                    const float go = sG[e_row * 33 + 16 + e_jj];
                    const float gc = sG[e_row * 33 + 24 + e_jj];
                    const float cin = fsig(gf) * ci_r + fsig(gi) * ftanh(gc);
                    const float hin = fsig(go) * ftanh(cin);
                    const float hn  = so_r * ftanh(hin);
                    ci_r = cin;
                    c_r  = hin;                            // carry: c <- hi_n
                    split2(hin, d_hihi[par ^ 1][e_idx], d_hilo[par ^ 1][e_idx]);
                    split2(hn,  d_hhi[e_idx], d_hlo[e_idx]);
                    if (l == 0) {
                        split2(hn, d_y0hi[(size_t)t * BHN + e_idx], d_y0lo[(size_t)t * BHN + e_idx]);
                    } else {
                        out[(size_t)t * BHN + e_idx] = hn;
                    }
                }
            }
            gsync(epoch, cta);   // h/hi planes complete before next step
        }
    }
}

extern "C" void kernel_launch(void* const* d_in, const int* in_sizes, int n_in,
                              void* d_out, int out_size)
{
    const float* x  = (const float*)d_in[0];   // (T,B,C)
    const float* h0 = (const float*)d_in[1];   // (L,4,B,H)
    const float* Wg = (const float*)d_in[2];   // (L,4H,C+H)
    const float* bg = (const float*)d_in[3];   // (L,4H)
    const float* Wi = (const float*)d_in[4];   // (L,4H,2H)
    const float* bi = (const float*)d_in[5];   // (L,4H)
    float* out = (float*)d_out;                // (T,B,H) f32

    cudaFuncSetAttribute(nested_lstm_persistent,
                         cudaFuncAttributeMaxDynamicSharedMemorySize, SMEM_DYN);
    reset_bar_kernel<<<1, 1>>>();
    nested_lstm_persistent<<<NCTA, NTH, SMEM_DYN>>>(x, h0, Wg, bg, Wi, bi, out);
}